// round 6
// baseline (speedup 1.0000x reference)
#include <cuda_runtime.h>
#include <cstdint>
#include <cstddef>

namespace {
constexpr int B2  = 2;
constexpr int SEQ = 2048;
constexpr int DM  = 512;
constexpr int NH  = 8;
constexpr int DKH = 64;
constexpr int MM  = B2 * SEQ;              // 4096
constexpr float INV_TEMP = 0.04419417382415922f;  // 1/sqrt(512)
constexpr float LN_EPS = 1e-5f;
}

// Scratch (device globals — allocations are forbidden)
__device__ float g_Q[MM * DM];
__device__ float g_K[MM * DM];
__device__ float g_V[MM * DM];
__device__ float g_ctx[MM * DM];
__device__ float g_x[MM * DM];
__device__ float g_invl[NH * B2 * SEQ];

__device__ __forceinline__ float tf32r(float x) {
  uint32_t o;
  asm("cvt.rna.tf32.f32 %0, %1;" : "=r"(o) : "f"(x));
  return __uint_as_float(o);
}

__device__ __forceinline__ void mma8(float* c, const uint32_t* a, const uint32_t* b) {
  asm volatile(
      "mma.sync.aligned.m16n8k8.row.col.f32.tf32.tf32.f32 "
      "{%0,%1,%2,%3}, {%4,%5,%6,%7}, {%8,%9}, {%0,%1,%2,%3};"
      : "+f"(c[0]), "+f"(c[1]), "+f"(c[2]), "+f"(c[3])
      : "r"(a[0]), "r"(a[1]), "r"(a[2]), "r"(a[3]), "r"(b[0]), "r"(b[1]));
}

// Paired layout: within each 8-wide k-group, logical i stored at ((i&3)<<1)|(i>>2)
// so fragment pair (tig, tig+4) sits at (2tig, 2tig+1) -> one LDS.64.

// ---------------------------------------------------------------------------
// Dense GEMM, 1xTF32: out = X @ W^T + bias (+resid). CTA 128x128, 8 warps
// (4m x 2n), warp 32x64, K-step 16. smem stride 18, paired k-layout.
// ---------------------------------------------------------------------------
__global__ __launch_bounds__(256) void gemm_mma(
    const float* __restrict__ X, const float* __restrict__ W,
    const float* __restrict__ bias, const float* __restrict__ resid,
    float* __restrict__ out) {
  __shared__ float As[128][18];
  __shared__ float Bs[128][18];
  const int tid = threadIdx.x;
  const int lane = tid & 31, wid = tid >> 5;
  const int g = lane >> 2, tig = lane & 3;
  const int wm = wid & 3, wn = wid >> 2;
  const int mbase = blockIdx.y << 7;
  const int nbase = blockIdx.x << 7;

  float c[2][8][4] = {};

  for (int kb = 0; kb < DM; kb += 16) {
#pragma unroll
    for (int j = 0; j < 2; j++) {
      int idx = tid + (j << 8);
      int row = idx & 127;
      int c4  = (idx >> 7) << 2;               // 0,4 (j=0) / 8,12 (j=1)
      int base = (c4 & ~7) + ((c4 & 4) >> 2);  // paired layout base
      float4 v = *reinterpret_cast<const float4*>(&X[(size_t)(mbase + row) * DM + kb + c4]);
      As[row][base + 0] = tf32r(v.x); As[row][base + 2] = tf32r(v.y);
      As[row][base + 4] = tf32r(v.z); As[row][base + 6] = tf32r(v.w);
      float4 w = *reinterpret_cast<const float4*>(&W[(size_t)(nbase + row) * DM + kb + c4]);
      Bs[row][base + 0] = tf32r(w.x); Bs[row][base + 2] = tf32r(w.y);
      Bs[row][base + 4] = tf32r(w.z); Bs[row][base + 6] = tf32r(w.w);
    }
    __syncthreads();

#pragma unroll
    for (int kk = 0; kk < 16; kk += 8) {
      uint32_t a[2][4], b[8][2];
#pragma unroll
      for (int mt = 0; mt < 2; mt++) {
        int r = (wm << 5) + (mt << 4) + g;
        float2 lo = *reinterpret_cast<const float2*>(&As[r][kk + (tig << 1)]);
        float2 hi = *reinterpret_cast<const float2*>(&As[r + 8][kk + (tig << 1)]);
        a[mt][0] = __float_as_uint(lo.x); a[mt][2] = __float_as_uint(lo.y);
        a[mt][1] = __float_as_uint(hi.x); a[mt][3] = __float_as_uint(hi.y);
      }
#pragma unroll
      for (int nt = 0; nt < 8; nt++) {
        int cc = (wn << 6) + (nt << 3) + g;
        float2 bv = *reinterpret_cast<const float2*>(&Bs[cc][kk + (tig << 1)]);
        b[nt][0] = __float_as_uint(bv.x); b[nt][1] = __float_as_uint(bv.y);
      }
#pragma unroll
      for (int mt = 0; mt < 2; mt++)
#pragma unroll
        for (int nt = 0; nt < 8; nt++)
          mma8(c[mt][nt], a[mt], b[nt]);
    }
    __syncthreads();
  }

#pragma unroll
  for (int mt = 0; mt < 2; mt++) {
    int r = mbase + (wm << 5) + (mt << 4) + g;
#pragma unroll
    for (int nt = 0; nt < 8; nt++) {
      int cc = nbase + (wn << 6) + (nt << 3) + (tig << 1);
      float2 bv = *reinterpret_cast<const float2*>(&bias[cc]);
      float o0 = c[mt][nt][0] + bv.x, o1 = c[mt][nt][1] + bv.y;
      float o2 = c[mt][nt][2] + bv.x, o3 = c[mt][nt][3] + bv.y;
      if (resid != nullptr) {
        float2 r0 = *reinterpret_cast<const float2*>(&resid[(size_t)r * DM + cc]);
        float2 r1 = *reinterpret_cast<const float2*>(&resid[(size_t)(r + 8) * DM + cc]);
        o0 += r0.x; o1 += r0.y; o2 += r1.x; o3 += r1.y;
      }
      float2 w0 = {o0, o1}, w1 = {o2, o3};
      *reinterpret_cast<float2*>(&out[(size_t)r * DM + cc]) = w0;
      *reinterpret_cast<float2*>(&out[(size_t)(r + 8) * DM + cc]) = w1;
    }
  }
}

// ---------------------------------------------------------------------------
// Single-sweep fused attention, TF32 mma, paired layouts.
// CTA = 128 q x one (b,h), 8 warps (4q x 2n), warp 32x32 per phase.
// Writes UNNORMALIZED exp to attn_out; ctx scaled in epilogue; g_invl saved.
// smem (105984B): Qs[128][68] Ks[64][68] Vt[64][68] Es[128][68] red sinv
// ---------------------------------------------------------------------------
__global__ __launch_bounds__(256, 2) void attn_mma(float* __restrict__ attn_out) {
  extern __shared__ float sm[];
  float (*Qs)[68] = reinterpret_cast<float(*)[68]>(sm);
  float (*Ks)[68] = reinterpret_cast<float(*)[68]>(sm + 8704);
  float (*Vt)[68] = reinterpret_cast<float(*)[68]>(sm + 13056);
  float (*Es)[68] = reinterpret_cast<float(*)[68]>(sm + 17408);
  float (*red)[2] = reinterpret_cast<float(*)[2]>(sm + 26112);
  float* sinv = sm + 26368;

  const int tid = threadIdx.x;
  const int lane = tid & 31, wid = tid >> 5;
  const int g = lane >> 2, tig = lane & 3;
  const int wq = wid >> 1, wn = wid & 1;       // 4q x 2n warps
  const int bh = blockIdx.y;                   // h*2 + b
  const int h = bh >> 1, b = bh & 1;
  const int qbase = blockIdx.x << 7;

  const float* Qg = g_Q + (size_t)(b * SEQ + qbase) * DM + h * DKH;
  const float* Kg = g_K + (size_t)(b * SEQ) * DM + h * DKH;
  const float* Vg = g_V + (size_t)(b * SEQ) * DM + h * DKH;

  // Stage Q once (paired d-layout)
#pragma unroll
  for (int j = 0; j < 8; j++) {
    int idx = tid + (j << 8);
    int row = idx >> 4, c4 = (idx & 15) << 2;
    int base = (c4 & ~7) + ((c4 & 4) >> 2);
    float4 v = *reinterpret_cast<const float4*>(&Qg[(size_t)row * DM + c4]);
    Qs[row][base + 0] = tf32r(v.x); Qs[row][base + 2] = tf32r(v.y);
    Qs[row][base + 4] = tf32r(v.z); Qs[row][base + 6] = tf32r(v.w);
  }
  __syncthreads();

  float rs[2][2] = {};
  float cx[2][4][4] = {};

  for (int kb = 0; kb < SEQ; kb += 64) {
    // Stage K (paired d-layout)
#pragma unroll
    for (int j = 0; j < 4; j++) {
      int idx = tid + (j << 8);
      int row = idx >> 4, c4 = (idx & 15) << 2;
      int base = (c4 & ~7) + ((c4 & 4) >> 2);
      float4 v = *reinterpret_cast<const float4*>(&Kg[(size_t)(kb + row) * DM + c4]);
      Ks[row][base + 0] = tf32r(v.x); Ks[row][base + 2] = tf32r(v.y);
      Ks[row][base + 4] = tf32r(v.z); Ks[row][base + 6] = tf32r(v.w);
    }
    // Stage V transposed [dv][key], key dim paired
#pragma unroll
    for (int j = 0; j < 4; j++) {
      int idx = tid + (j << 8);
      int key = idx & 63, c4 = (idx >> 6) << 2;
      int kcol = (key & ~7) + (((key & 3) << 1) | ((key & 7) >> 2));
      float4 v = *reinterpret_cast<const float4*>(&Vg[(size_t)(kb + key) * DM + c4]);
      Vt[c4 + 0][kcol] = tf32r(v.x);
      Vt[c4 + 1][kcol] = tf32r(v.y);
      Vt[c4 + 2][kcol] = tf32r(v.z);
      Vt[c4 + 3][kcol] = tf32r(v.w);
    }
    __syncthreads();

    // Scores: S = Q @ K^T (paired LDS.64 fragment loads)
    float s[2][4][4] = {};
#pragma unroll
    for (int d8 = 0; d8 < 64; d8 += 8) {
      uint32_t a[2][4], bb[4][2];
#pragma unroll
      for (int mt = 0; mt < 2; mt++) {
        int r = (wq << 5) + (mt << 4) + g;
        float2 lo = *reinterpret_cast<const float2*>(&Qs[r][d8 + (tig << 1)]);
        float2 hi = *reinterpret_cast<const float2*>(&Qs[r + 8][d8 + (tig << 1)]);
        a[mt][0] = __float_as_uint(lo.x); a[mt][2] = __float_as_uint(lo.y);
        a[mt][1] = __float_as_uint(hi.x); a[mt][3] = __float_as_uint(hi.y);
      }
#pragma unroll
      for (int nt = 0; nt < 4; nt++) {
        int cc = (wn << 5) + (nt << 3) + g;
        float2 bv = *reinterpret_cast<const float2*>(&Ks[cc][d8 + (tig << 1)]);
        bb[nt][0] = __float_as_uint(bv.x); bb[nt][1] = __float_as_uint(bv.y);
      }
#pragma unroll
      for (int mt = 0; mt < 2; mt++)
#pragma unroll
        for (int nt = 0; nt < 4; nt++)
          mma8(s[mt][nt], a[mt], bb[nt]);
    }

    // Unnormalized exp -> gmem + Es (paired key layout); accumulate rowsums
#pragma unroll
    for (int mt = 0; mt < 2; mt++) {
      int r0 = (wq << 5) + (mt << 4) + g;
#pragma unroll
      for (int nt = 0; nt < 4; nt++) {
        int kgrp = (wn << 5) + (nt << 3);
        int i0 = tig << 1, i1 = i0 + 1;
        int sc0 = kgrp + (((i0 & 3) << 1) | (i0 >> 2));
        int sc1 = kgrp + (((i1 & 3) << 1) | (i1 >> 2));
        float e0 = __expf(s[mt][nt][0] * INV_TEMP);
        float e1 = __expf(s[mt][nt][1] * INV_TEMP);
        float e2 = __expf(s[mt][nt][2] * INV_TEMP);
        float e3 = __expf(s[mt][nt][3] * INV_TEMP);
        rs[mt][0] += e0 + e1;
        rs[mt][1] += e2 + e3;
        size_t go = ((size_t)bh * SEQ + qbase + r0) * SEQ + kb + kgrp + i0;
        float2 w0 = {e0, e1}, w1 = {e2, e3};
        *reinterpret_cast<float2*>(&attn_out[go]) = w0;
        *reinterpret_cast<float2*>(&attn_out[go + (size_t)8 * SEQ]) = w1;
        Es[r0][sc0] = tf32r(e0);     Es[r0][sc1] = tf32r(e1);
        Es[r0 + 8][sc0] = tf32r(e2); Es[r0 + 8][sc1] = tf32r(e3);
      }
    }
    __syncthreads();

    // ctx += E @ V (paired LDS.64 loads)
#pragma unroll
    for (int k8 = 0; k8 < 64; k8 += 8) {
      uint32_t a[2][4], bb[4][2];
#pragma unroll
      for (int mt = 0; mt < 2; mt++) {
        int r = (wq << 5) + (mt << 4) + g;
        float2 lo = *reinterpret_cast<const float2*>(&Es[r][k8 + (tig << 1)]);
        float2 hi = *reinterpret_cast<const float2*>(&Es[r + 8][k8 + (tig << 1)]);
        a[mt][0] = __float_as_uint(lo.x); a[mt][2] = __float_as_uint(lo.y);
        a[mt][1] = __float_as_uint(hi.x); a[mt][3] = __float_as_uint(hi.y);
      }
#pragma unroll
      for (int nt = 0; nt < 4; nt++) {
        int cc = (wn << 5) + (nt << 3) + g;
        float2 bv = *reinterpret_cast<const float2*>(&Vt[cc][k8 + (tig << 1)]);
        bb[nt][0] = __float_as_uint(bv.x); bb[nt][1] = __float_as_uint(bv.y);
      }
#pragma unroll
      for (int mt = 0; mt < 2; mt++)
#pragma unroll
        for (int nt = 0; nt < 4; nt++)
          mma8(cx[mt][nt], a[mt], bb[nt]);
    }
    __syncthreads();
  }

  // Reduce rowsums across tig lanes, then across the 2 n-warps
#pragma unroll
  for (int mt = 0; mt < 2; mt++)
#pragma unroll
    for (int u = 0; u < 2; u++) {
      rs[mt][u] += __shfl_xor_sync(0xffffffffu, rs[mt][u], 1);
      rs[mt][u] += __shfl_xor_sync(0xffffffffu, rs[mt][u], 2);
    }
  if (tig == 0) {
#pragma unroll
    for (int mt = 0; mt < 2; mt++)
#pragma unroll
      for (int u = 0; u < 2; u++)
        red[(wq << 5) + (mt << 4) + (u << 3) + g][wn] = rs[mt][u];
  }
  __syncthreads();
  if (tid < 128) {
    float inv = 1.0f / (red[tid][0] + red[tid][1]);
    sinv[tid] = inv;
    g_invl[(size_t)bh * SEQ + qbase + tid] = inv;
  }
  __syncthreads();

  // Scale ctx and write (merged heads layout)
#pragma unroll
  for (int mt = 0; mt < 2; mt++) {
    int rq = (wq << 5) + (mt << 4) + g;
    float i0 = sinv[rq], i1 = sinv[rq + 8];
    int r = b * SEQ + qbase + rq;
#pragma unroll
    for (int nt = 0; nt < 4; nt++) {
      int cc = h * DKH + (wn << 5) + (nt << 3) + (tig << 1);
      float2 w0 = {cx[mt][nt][0] * i0, cx[mt][nt][1] * i0};
      float2 w1 = {cx[mt][nt][2] * i1, cx[mt][nt][3] * i1};
      *reinterpret_cast<float2*>(&g_ctx[(size_t)r * DM + cc]) = w0;
      *reinterpret_cast<float2*>(&g_ctx[(size_t)(r + 8) * DM + cc]) = w1;
    }
  }
}

// ---------------------------------------------------------------------------
// Normalize attn buffer in place: one float4 per thread. row = i >> 9.
// ---------------------------------------------------------------------------
__global__ __launch_bounds__(256) void attn_norm(float* __restrict__ attn) {
  size_t i = (size_t)blockIdx.x * 256 + threadIdx.x;   // float4 index
  size_t row = i >> 9;
  float s = __ldg(&g_invl[row]);
  float4* p = reinterpret_cast<float4*>(attn) + i;
  float4 v = *p;
  v.x *= s; v.y *= s; v.z *= s; v.w *= s;
  *p = v;
}

// ---------------------------------------------------------------------------
// LayerNorm over last dim (512), one block per row.
// ---------------------------------------------------------------------------
__global__ __launch_bounds__(256) void ln_kernel(
    const float* __restrict__ gamma, const float* __restrict__ beta,
    float* __restrict__ y) {
  __shared__ float warp_s[8], warp_q[8];
  __shared__ float s_mu, s_rstd;
  const int row = blockIdx.x;
  const int tid = threadIdx.x;
  const float* x = g_x + (size_t)row * DM;

  float v0 = x[tid], v1 = x[tid + 256];
  float s = v0 + v1;
  float q = v0 * v0 + v1 * v1;
#pragma unroll
  for (int o = 16; o > 0; o >>= 1) {
    s += __shfl_xor_sync(0xffffffffu, s, o);
    q += __shfl_xor_sync(0xffffffffu, q, o);
  }
  if ((tid & 31) == 0) { warp_s[tid >> 5] = s; warp_q[tid >> 5] = q; }
  __syncthreads();
  if (tid == 0) {
    float ss = 0.f, qq = 0.f;
#pragma unroll
    for (int i = 0; i < 8; i++) { ss += warp_s[i]; qq += warp_q[i]; }
    float mu = ss * (1.0f / DM);
    float var = qq * (1.0f / DM) - mu * mu;
    s_mu = mu;
    s_rstd = rsqrtf(var + LN_EPS);
  }
  __syncthreads();
  float mu = s_mu, r = s_rstd;
  y[(size_t)row * DM + tid]       = (v0 - mu) * r * gamma[tid] + beta[tid];
  y[(size_t)row * DM + tid + 256] = (v1 - mu) * r * gamma[tid + 256] + beta[tid + 256];
}

// ---------------------------------------------------------------------------
extern "C" void kernel_launch(void* const* d_in, const int* in_sizes, int n_in,
                              void* d_out, int out_size) {
  const float* q     = (const float*)d_in[0];
  const float* k     = (const float*)d_in[1];
  const float* v     = (const float*)d_in[2];
  const float* Wq    = (const float*)d_in[3];
  const float* bq    = (const float*)d_in[4];
  const float* Wk    = (const float*)d_in[5];
  const float* bk    = (const float*)d_in[6];
  const float* Wv    = (const float*)d_in[7];
  const float* bv    = (const float*)d_in[8];
  const float* Wfc   = (const float*)d_in[9];
  const float* bfc   = (const float*)d_in[10];
  const float* gamma = (const float*)d_in[11];
  const float* beta  = (const float*)d_in[12];

  float* out = (float*)d_out;                       // y: [2,2048,512]
  float* attn_out = out + (size_t)MM * DM;          // attn: [16,2048,2048]

  float *gQ, *gK, *gV, *gctx, *gx;
  cudaGetSymbolAddress((void**)&gQ, g_Q);
  cudaGetSymbolAddress((void**)&gK, g_K);
  cudaGetSymbolAddress((void**)&gV, g_V);
  cudaGetSymbolAddress((void**)&gctx, g_ctx);
  cudaGetSymbolAddress((void**)&gx, g_x);

  cudaFuncSetAttribute(attn_mma, cudaFuncAttributeMaxDynamicSharedMemorySize, 105984);

  dim3 gg(DM / 128, MM / 128);     // (4, 32) = 128 CTAs
  gemm_mma<<<gg, 256>>>(q, Wq, bq, nullptr, gQ);
  gemm_mma<<<gg, 256>>>(k, Wk, bk, nullptr, gK);
  gemm_mma<<<gg, 256>>>(v, Wv, bv, nullptr, gV);

  dim3 ga(SEQ / 128, NH * B2);     // (16, 16)
  attn_mma<<<ga, 256, 105984>>>(attn_out);

  size_t total4 = (size_t)NH * B2 * SEQ * SEQ / 4;  // 16,777,216
  attn_norm<<<(unsigned)(total4 / 256), 256>>>(attn_out);

  gemm_mma<<<gg, 256>>>(gctx, Wfc, bfc, q, gx);
  ln_kernel<<<MM, 256>>>(gamma, beta, out);
}

// round 7
// speedup vs baseline: 1.2983x; 1.2983x over previous
#include <cuda_runtime.h>
#include <cstdint>
#include <cstddef>

namespace {
constexpr int B2  = 2;
constexpr int SEQ = 2048;
constexpr int DM  = 512;
constexpr int NH  = 8;
constexpr int DKH = 64;
constexpr int MM  = B2 * SEQ;              // 4096
constexpr float INV_TEMP = 0.04419417382415922f;  // 1/sqrt(512)
constexpr float LN_EPS = 1e-5f;
}

// Scratch (device globals — allocations are forbidden)
__device__ float g_Q[MM * DM];
__device__ float g_K[MM * DM];
__device__ float g_V[MM * DM];
__device__ float g_ctx[MM * DM];
__device__ float g_x[MM * DM];

__device__ __forceinline__ float tf32r(float x) {
  uint32_t o;
  asm("cvt.rna.tf32.f32 %0, %1;" : "=r"(o) : "f"(x));
  return __uint_as_float(o);
}

__device__ __forceinline__ void mma8(float* c, const uint32_t* a, const uint32_t* b) {
  asm volatile(
      "mma.sync.aligned.m16n8k8.row.col.f32.tf32.tf32.f32 "
      "{%0,%1,%2,%3}, {%4,%5,%6,%7}, {%8,%9}, {%0,%1,%2,%3};"
      : "+f"(c[0]), "+f"(c[1]), "+f"(c[2]), "+f"(c[3])
      : "r"(a[0]), "r"(a[1]), "r"(a[2]), "r"(a[3]), "r"(b[0]), "r"(b[1]));
}

// ldmatrix x4 on 32-bit data: each 8x8 b16 tile == 8 rows x 4 floats.
// lane l receives M32[l/4][l%4] of its tile -> exact tf32 fragment layout.
__device__ __forceinline__ void ldsm4(uint32_t* r, uint32_t addr) {
  asm volatile("ldmatrix.sync.aligned.m8n8.x4.shared.b16 {%0,%1,%2,%3}, [%4];"
               : "=r"(r[0]), "=r"(r[1]), "=r"(r[2]), "=r"(r[3]) : "r"(addr));
}

__device__ __forceinline__ uint32_t smem_u32(const void* p) {
  return (uint32_t)__cvta_generic_to_shared(p);
}

// ---------------------------------------------------------------------------
// Dense GEMM, 1xTF32 + ldmatrix: out = X @ W^T + bias (+resid).
// CTA 128x128, 8 warps (4m x 2n), warp 32x64, K-step 16. smem stride 20.
// ---------------------------------------------------------------------------
__global__ __launch_bounds__(256) void gemm_mma(
    const float* __restrict__ X, const float* __restrict__ W,
    const float* __restrict__ bias, const float* __restrict__ resid,
    float* __restrict__ out) {
  __shared__ float As[128][20];
  __shared__ float Bs[128][20];
  const int tid = threadIdx.x;
  const int lane = tid & 31, wid = tid >> 5;
  const int g = lane >> 2, tig = lane & 3;
  const int wm = wid & 3, wn = wid >> 2;
  const int mbase = blockIdx.y << 7;
  const int nbase = blockIdx.x << 7;

  // ldmatrix per-lane offsets (bytes), stride 20 floats
  const int rowA = (lane & 7) + ((lane >> 3) & 1) * 8;   // A tiles: 0,1=rows; 2,3=+4cols
  const uint32_t offA = (uint32_t)((rowA * 20 + ((lane >> 4) << 2)) << 2);
  const int rowB = (lane & 7) + ((lane >> 4) << 3);      // B tiles: 0,1=cols; 2,3=+8rows
  const uint32_t offB = (uint32_t)((rowB * 20 + (((lane >> 3) & 1) << 2)) << 2);

  uint32_t aAddr[2], bAddr[4];
#pragma unroll
  for (int mt = 0; mt < 2; mt++)
    aAddr[mt] = smem_u32(&As[0][0]) + offA + (uint32_t)(((wm << 5) + (mt << 4)) * 80);
#pragma unroll
  for (int p = 0; p < 4; p++)
    bAddr[p] = smem_u32(&Bs[0][0]) + offB + (uint32_t)(((wn << 6) + (p << 4)) * 80);

  float c[2][8][4] = {};

  for (int kb = 0; kb < DM; kb += 16) {
#pragma unroll
    for (int j = 0; j < 2; j++) {
      int idx = tid + (j << 8);
      int row = idx & 127;
      int c4  = (idx >> 7) << 2;
      float4 v = *reinterpret_cast<const float4*>(&X[(size_t)(mbase + row) * DM + kb + c4]);
      v.x = tf32r(v.x); v.y = tf32r(v.y); v.z = tf32r(v.z); v.w = tf32r(v.w);
      *reinterpret_cast<float4*>(&As[row][c4]) = v;
      float4 w = *reinterpret_cast<const float4*>(&W[(size_t)(nbase + row) * DM + kb + c4]);
      w.x = tf32r(w.x); w.y = tf32r(w.y); w.z = tf32r(w.z); w.w = tf32r(w.w);
      *reinterpret_cast<float4*>(&Bs[row][c4]) = w;
    }
    __syncthreads();

#pragma unroll
    for (int kk = 0; kk < 16; kk += 8) {
      uint32_t af[2][4], bf[4][4];
#pragma unroll
      for (int mt = 0; mt < 2; mt++) ldsm4(af[mt], aAddr[mt] + (kk << 2));
#pragma unroll
      for (int p = 0; p < 4; p++) ldsm4(bf[p], bAddr[p] + (kk << 2));
#pragma unroll
      for (int mt = 0; mt < 2; mt++)
#pragma unroll
        for (int p = 0; p < 4; p++) {
          mma8(c[mt][2 * p],     af[mt], &bf[p][0]);
          mma8(c[mt][2 * p + 1], af[mt], &bf[p][2]);
        }
    }
    __syncthreads();
  }

#pragma unroll
  for (int mt = 0; mt < 2; mt++) {
    int r = mbase + (wm << 5) + (mt << 4) + g;
#pragma unroll
    for (int nt = 0; nt < 8; nt++) {
      int cc = nbase + (wn << 6) + (nt << 3) + (tig << 1);
      float2 bv = *reinterpret_cast<const float2*>(&bias[cc]);
      float o0 = c[mt][nt][0] + bv.x, o1 = c[mt][nt][1] + bv.y;
      float o2 = c[mt][nt][2] + bv.x, o3 = c[mt][nt][3] + bv.y;
      if (resid != nullptr) {
        float2 r0 = *reinterpret_cast<const float2*>(&resid[(size_t)r * DM + cc]);
        float2 r1 = *reinterpret_cast<const float2*>(&resid[(size_t)(r + 8) * DM + cc]);
        o0 += r0.x; o1 += r0.y; o2 += r1.x; o3 += r1.y;
      }
      float2 w0 = {o0, o1}, w1 = {o2, o3};
      *reinterpret_cast<float2*>(&out[(size_t)r * DM + cc]) = w0;
      *reinterpret_cast<float2*>(&out[(size_t)(r + 8) * DM + cc]) = w1;
    }
  }
}

// ---------------------------------------------------------------------------
// Two-sweep fused attention, TF32 mma + ldmatrix. CTA = 128 q x one (b,h),
// 8 warps (4q x 2n), warp 32x32. Sweep 1: rowsums. Sweep 2: normalized attn
// write (once!) + ctx = E @ V.
// smem (105984B): Qs[128][68] Ks[64][68] Vt[64][68] Es[128][68] red sinv
// ---------------------------------------------------------------------------
__global__ __launch_bounds__(256, 2) void attn_mma(float* __restrict__ attn_out) {
  extern __shared__ float sm[];
  float (*Qs)[68] = reinterpret_cast<float(*)[68]>(sm);
  float (*Ks)[68] = reinterpret_cast<float(*)[68]>(sm + 8704);
  float (*Vt)[68] = reinterpret_cast<float(*)[68]>(sm + 13056);
  float (*Es)[68] = reinterpret_cast<float(*)[68]>(sm + 17408);
  float (*red)[2] = reinterpret_cast<float(*)[2]>(sm + 26112);
  float* sinv = sm + 26368;

  const int tid = threadIdx.x;
  const int lane = tid & 31, wid = tid >> 5;
  const int g = lane >> 2, tig = lane & 3;
  const int wq = wid >> 1, wn = wid & 1;       // 4q x 2n warps
  const int bh = blockIdx.y;                   // h*2 + b
  const int h = bh >> 1, b = bh & 1;
  const int qbase = blockIdx.x << 7;

  const float* Qg = g_Q + (size_t)(b * SEQ + qbase) * DM + h * DKH;
  const float* Kg = g_K + (size_t)(b * SEQ) * DM + h * DKH;
  const float* Vg = g_V + (size_t)(b * SEQ) * DM + h * DKH;

  // ldmatrix per-lane offsets (bytes), stride 68 floats = 272B
  const int rowA = (lane & 7) + ((lane >> 3) & 1) * 8;
  const uint32_t offA = (uint32_t)((rowA * 68 + ((lane >> 4) << 2)) << 2);
  const int rowB = (lane & 7) + ((lane >> 4) << 3);
  const uint32_t offB = (uint32_t)((rowB * 68 + (((lane >> 3) & 1) << 2)) << 2);

  uint32_t qAddr[2], kAddr[2], eAddr[2], vAddr[2];
#pragma unroll
  for (int mt = 0; mt < 2; mt++) {
    uint32_t moff = (uint32_t)(((wq << 5) + (mt << 4)) * 272);
    qAddr[mt] = smem_u32(&Qs[0][0]) + offA + moff;
    eAddr[mt] = smem_u32(&Es[0][0]) + offA + moff;
  }
#pragma unroll
  for (int p = 0; p < 2; p++) {
    uint32_t noff = (uint32_t)(((wn << 5) + (p << 4)) * 272);
    kAddr[p] = smem_u32(&Ks[0][0]) + offB + noff;
    vAddr[p] = smem_u32(&Vt[0][0]) + offB + noff;
  }

  // Stage Q once
#pragma unroll
  for (int j = 0; j < 8; j++) {
    int idx = tid + (j << 8);
    int row = idx >> 4, c4 = (idx & 15) << 2;
    float4 v = *reinterpret_cast<const float4*>(&Qg[(size_t)row * DM + c4]);
    v.x = tf32r(v.x); v.y = tf32r(v.y); v.z = tf32r(v.z); v.w = tf32r(v.w);
    *reinterpret_cast<float4*>(&Qs[row][c4]) = v;
  }
  __syncthreads();

  // ---------------- sweep 1: rowsums ----------------
  float rs[2][2] = {};
  for (int kb = 0; kb < SEQ; kb += 64) {
#pragma unroll
    for (int j = 0; j < 4; j++) {
      int idx = tid + (j << 8);
      int row = idx >> 4, c4 = (idx & 15) << 2;
      float4 v = *reinterpret_cast<const float4*>(&Kg[(size_t)(kb + row) * DM + c4]);
      v.x = tf32r(v.x); v.y = tf32r(v.y); v.z = tf32r(v.z); v.w = tf32r(v.w);
      *reinterpret_cast<float4*>(&Ks[row][c4]) = v;
    }
    __syncthreads();

    float s[2][4][4] = {};
#pragma unroll
    for (int d8 = 0; d8 < 64; d8 += 8) {
      uint32_t af[2][4], bf[2][4];
#pragma unroll
      for (int mt = 0; mt < 2; mt++) ldsm4(af[mt], qAddr[mt] + (d8 << 2));
#pragma unroll
      for (int p = 0; p < 2; p++) ldsm4(bf[p], kAddr[p] + (d8 << 2));
#pragma unroll
      for (int mt = 0; mt < 2; mt++)
#pragma unroll
        for (int p = 0; p < 2; p++) {
          mma8(s[mt][2 * p],     af[mt], &bf[p][0]);
          mma8(s[mt][2 * p + 1], af[mt], &bf[p][2]);
        }
    }
#pragma unroll
    for (int mt = 0; mt < 2; mt++)
#pragma unroll
      for (int nt = 0; nt < 4; nt++) {
        rs[mt][0] += __expf(s[mt][nt][0] * INV_TEMP) + __expf(s[mt][nt][1] * INV_TEMP);
        rs[mt][1] += __expf(s[mt][nt][2] * INV_TEMP) + __expf(s[mt][nt][3] * INV_TEMP);
      }
    __syncthreads();
  }

  // Reduce rowsums across tig lanes, then across the 2 n-warps
#pragma unroll
  for (int mt = 0; mt < 2; mt++)
#pragma unroll
    for (int u = 0; u < 2; u++) {
      rs[mt][u] += __shfl_xor_sync(0xffffffffu, rs[mt][u], 1);
      rs[mt][u] += __shfl_xor_sync(0xffffffffu, rs[mt][u], 2);
    }
  if (tig == 0) {
#pragma unroll
    for (int mt = 0; mt < 2; mt++)
#pragma unroll
      for (int u = 0; u < 2; u++)
        red[(wq << 5) + (mt << 4) + (u << 3) + g][wn] = rs[mt][u];
  }
  __syncthreads();
  if (tid < 128) sinv[tid] = 1.0f / (red[tid][0] + red[tid][1]);
  __syncthreads();

  float inv[2][2];
#pragma unroll
  for (int mt = 0; mt < 2; mt++) {
    inv[mt][0] = sinv[(wq << 5) + (mt << 4) + g];
    inv[mt][1] = sinv[(wq << 5) + (mt << 4) + 8 + g];
  }

  // ---------------- sweep 2: normalized attn + context ----------------
  float cx[2][4][4] = {};
  for (int kb = 0; kb < SEQ; kb += 64) {
#pragma unroll
    for (int j = 0; j < 4; j++) {
      int idx = tid + (j << 8);
      int row = idx >> 4, c4 = (idx & 15) << 2;
      float4 v = *reinterpret_cast<const float4*>(&Kg[(size_t)(kb + row) * DM + c4]);
      v.x = tf32r(v.x); v.y = tf32r(v.y); v.z = tf32r(v.z); v.w = tf32r(v.w);
      *reinterpret_cast<float4*>(&Ks[row][c4]) = v;
    }
    // V transposed [dv][key]; 32 consecutive keys per warp-phase -> conflict-free
#pragma unroll
    for (int j = 0; j < 4; j++) {
      int idx = tid + (j << 8);
      int key = idx & 63, c4 = (idx >> 6) << 2;
      float4 v = *reinterpret_cast<const float4*>(&Vg[(size_t)(kb + key) * DM + c4]);
      Vt[c4 + 0][key] = tf32r(v.x);
      Vt[c4 + 1][key] = tf32r(v.y);
      Vt[c4 + 2][key] = tf32r(v.z);
      Vt[c4 + 3][key] = tf32r(v.w);
    }
    __syncthreads();

    // Scores
    float s[2][4][4] = {};
#pragma unroll
    for (int d8 = 0; d8 < 64; d8 += 8) {
      uint32_t af[2][4], bf[2][4];
#pragma unroll
      for (int mt = 0; mt < 2; mt++) ldsm4(af[mt], qAddr[mt] + (d8 << 2));
#pragma unroll
      for (int p = 0; p < 2; p++) ldsm4(bf[p], kAddr[p] + (d8 << 2));
#pragma unroll
      for (int mt = 0; mt < 2; mt++)
#pragma unroll
        for (int p = 0; p < 2; p++) {
          mma8(s[mt][2 * p],     af[mt], &bf[p][0]);
          mma8(s[mt][2 * p + 1], af[mt], &bf[p][2]);
        }
    }

    // exp, normalize, write gmem once + Es
#pragma unroll
    for (int mt = 0; mt < 2; mt++) {
      int r0 = (wq << 5) + (mt << 4) + g;
#pragma unroll
      for (int nt = 0; nt < 4; nt++) {
        int c0 = (wn << 5) + (nt << 3) + (tig << 1);
        float e0 = __expf(s[mt][nt][0] * INV_TEMP) * inv[mt][0];
        float e1 = __expf(s[mt][nt][1] * INV_TEMP) * inv[mt][0];
        float e2 = __expf(s[mt][nt][2] * INV_TEMP) * inv[mt][1];
        float e3 = __expf(s[mt][nt][3] * INV_TEMP) * inv[mt][1];
        size_t go = ((size_t)bh * SEQ + qbase + r0) * SEQ + kb + c0;
        float2 w0 = {e0, e1}, w1 = {e2, e3};
        *reinterpret_cast<float2*>(&attn_out[go]) = w0;
        *reinterpret_cast<float2*>(&attn_out[go + (size_t)8 * SEQ]) = w1;
        float2 t0 = {tf32r(e0), tf32r(e1)}, t1 = {tf32r(e2), tf32r(e3)};
        *reinterpret_cast<float2*>(&Es[r0][c0]) = t0;
        *reinterpret_cast<float2*>(&Es[r0 + 8][c0]) = t1;
      }
    }
    __syncthreads();

    // ctx += E @ V
#pragma unroll
    for (int k8 = 0; k8 < 64; k8 += 8) {
      uint32_t af[2][4], bf[2][4];
#pragma unroll
      for (int mt = 0; mt < 2; mt++) ldsm4(af[mt], eAddr[mt] + (k8 << 2));
#pragma unroll
      for (int p = 0; p < 2; p++) ldsm4(bf[p], vAddr[p] + (k8 << 2));
#pragma unroll
      for (int mt = 0; mt < 2; mt++)
#pragma unroll
        for (int p = 0; p < 2; p++) {
          mma8(cx[mt][2 * p],     af[mt], &bf[p][0]);
          mma8(cx[mt][2 * p + 1], af[mt], &bf[p][2]);
        }
    }
    __syncthreads();
  }

  // Write context (merged heads), already normalized
#pragma unroll
  for (int mt = 0; mt < 2; mt++) {
    int r = b * SEQ + qbase + (wq << 5) + (mt << 4) + g;
#pragma unroll
    for (int nt = 0; nt < 4; nt++) {
      int cc = h * DKH + (wn << 5) + (nt << 3) + (tig << 1);
      float2 w0 = {cx[mt][nt][0], cx[mt][nt][1]};
      float2 w1 = {cx[mt][nt][2], cx[mt][nt][3]};
      *reinterpret_cast<float2*>(&g_ctx[(size_t)r * DM + cc]) = w0;
      *reinterpret_cast<float2*>(&g_ctx[(size_t)(r + 8) * DM + cc]) = w1;
    }
  }
}

// ---------------------------------------------------------------------------
// LayerNorm over last dim (512), one block per row.
// ---------------------------------------------------------------------------
__global__ __launch_bounds__(256) void ln_kernel(
    const float* __restrict__ gamma, const float* __restrict__ beta,
    float* __restrict__ y) {
  __shared__ float warp_s[8], warp_q[8];
  __shared__ float s_mu, s_rstd;
  const int row = blockIdx.x;
  const int tid = threadIdx.x;
  const float* x = g_x + (size_t)row * DM;

  float v0 = x[tid], v1 = x[tid + 256];
  float s = v0 + v1;
  float q = v0 * v0 + v1 * v1;
#pragma unroll
  for (int o = 16; o > 0; o >>= 1) {
    s += __shfl_xor_sync(0xffffffffu, s, o);
    q += __shfl_xor_sync(0xffffffffu, q, o);
  }
  if ((tid & 31) == 0) { warp_s[tid >> 5] = s; warp_q[tid >> 5] = q; }
  __syncthreads();
  if (tid == 0) {
    float ss = 0.f, qq = 0.f;
#pragma unroll
    for (int i = 0; i < 8; i++) { ss += warp_s[i]; qq += warp_q[i]; }
    float mu = ss * (1.0f / DM);
    float var = qq * (1.0f / DM) - mu * mu;
    s_mu = mu;
    s_rstd = rsqrtf(var + LN_EPS);
  }
  __syncthreads();
  float mu = s_mu, r = s_rstd;
  y[(size_t)row * DM + tid]       = (v0 - mu) * r * gamma[tid] + beta[tid];
  y[(size_t)row * DM + tid + 256] = (v1 - mu) * r * gamma[tid + 256] + beta[tid + 256];
}

// ---------------------------------------------------------------------------
extern "C" void kernel_launch(void* const* d_in, const int* in_sizes, int n_in,
                              void* d_out, int out_size) {
  const float* q     = (const float*)d_in[0];
  const float* k     = (const float*)d_in[1];
  const float* v     = (const float*)d_in[2];
  const float* Wq    = (const float*)d_in[3];
  const float* bq    = (const float*)d_in[4];
  const float* Wk    = (const float*)d_in[5];
  const float* bk    = (const float*)d_in[6];
  const float* Wv    = (const float*)d_in[7];
  const float* bv    = (const float*)d_in[8];
  const float* Wfc   = (const float*)d_in[9];
  const float* bfc   = (const float*)d_in[10];
  const float* gamma = (const float*)d_in[11];
  const float* beta  = (const float*)d_in[12];

  float* out = (float*)d_out;                       // y: [2,2048,512]
  float* attn_out = out + (size_t)MM * DM;          // attn: [16,2048,2048]

  float *gQ, *gK, *gV, *gctx, *gx;
  cudaGetSymbolAddress((void**)&gQ, g_Q);
  cudaGetSymbolAddress((void**)&gK, g_K);
  cudaGetSymbolAddress((void**)&gV, g_V);
  cudaGetSymbolAddress((void**)&gctx, g_ctx);
  cudaGetSymbolAddress((void**)&gx, g_x);

  cudaFuncSetAttribute(attn_mma, cudaFuncAttributeMaxDynamicSharedMemorySize, 105984);

  dim3 gg(DM / 128, MM / 128);     // (4, 32) = 128 CTAs
  gemm_mma<<<gg, 256>>>(q, Wq, bq, nullptr, gQ);
  gemm_mma<<<gg, 256>>>(k, Wk, bk, nullptr, gK);
  gemm_mma<<<gg, 256>>>(v, Wv, bv, nullptr, gV);

  dim3 ga(SEQ / 128, NH * B2);     // (16, 16)
  attn_mma<<<ga, 256, 105984>>>(attn_out);

  gemm_mma<<<gg, 256>>>(gctx, Wfc, bfc, q, gx);
  ln_kernel<<<MM, 256>>>(gamma, beta, out);
}

// round 9
// speedup vs baseline: 1.3394x; 1.0317x over previous
#include <cuda_runtime.h>
#include <cstdint>
#include <cstddef>

namespace {
constexpr int B2  = 2;
constexpr int SEQ = 2048;
constexpr int DM  = 512;
constexpr int NH  = 8;
constexpr int DKH = 64;
constexpr int MM  = B2 * SEQ;              // 4096
constexpr float INV_TEMP = 0.04419417382415922f;  // 1/sqrt(512)
constexpr float LN_EPS = 1e-5f;
}

// Scratch (device globals — allocations are forbidden)
__device__ float g_Q[MM * DM];
__device__ float g_K[MM * DM];
__device__ float g_V[MM * DM];
__device__ float g_ctx[MM * DM];
__device__ float g_x[MM * DM];

__device__ __forceinline__ float tf32r(float x) {
  uint32_t o;
  asm("cvt.rna.tf32.f32 %0, %1;" : "=r"(o) : "f"(x));
  return __uint_as_float(o);
}

__device__ __forceinline__ void mma8(float* c, const uint32_t* a, const uint32_t* b) {
  asm volatile(
      "mma.sync.aligned.m16n8k8.row.col.f32.tf32.tf32.f32 "
      "{%0,%1,%2,%3}, {%4,%5,%6,%7}, {%8,%9}, {%0,%1,%2,%3};"
      : "+f"(c[0]), "+f"(c[1]), "+f"(c[2]), "+f"(c[3])
      : "r"(a[0]), "r"(a[1]), "r"(a[2]), "r"(a[3]), "r"(b[0]), "r"(b[1]));
}

__device__ __forceinline__ void ldsm4(uint32_t* r, uint32_t addr) {
  asm volatile("ldmatrix.sync.aligned.m8n8.x4.shared.b16 {%0,%1,%2,%3}, [%4];"
               : "=r"(r[0]), "=r"(r[1]), "=r"(r[2]), "=r"(r[3]) : "r"(addr));
}

__device__ __forceinline__ uint32_t smem_u32(const void* p) {
  return (uint32_t)__cvta_generic_to_shared(p);
}

__device__ __forceinline__ void cpa16(uint32_t dst, const void* src) {
  asm volatile("cp.async.cg.shared.global [%0], [%1], 16;" :: "r"(dst), "l"(src));
}
__device__ __forceinline__ void cpa_commit() {
  asm volatile("cp.async.commit_group;");
}
__device__ __forceinline__ void cpa_wait0() {
  asm volatile("cp.async.wait_group 0;");
}

// ---------------------------------------------------------------------------
// Dense GEMM, 1xTF32 + ldmatrix: out = X @ W^T + bias (+resid).
// CTA 128x128, 8 warps (4m x 2n), warp 32x64, K-step 16. smem stride 20.
// round_out: round output to tf32 (for Q/K/V feeding attention).
// ---------------------------------------------------------------------------
__global__ __launch_bounds__(256) void gemm_mma(
    const float* __restrict__ X, const float* __restrict__ W,
    const float* __restrict__ bias, const float* __restrict__ resid,
    float* __restrict__ out, int round_out) {
  __shared__ float As[128][20];
  __shared__ float Bs[128][20];
  const int tid = threadIdx.x;
  const int lane = tid & 31, wid = tid >> 5;
  const int g = lane >> 2, tig = lane & 3;
  const int wm = wid & 3, wn = wid >> 2;
  const int mbase = blockIdx.y << 7;
  const int nbase = blockIdx.x << 7;

  const int rowA = (lane & 7) + ((lane >> 3) & 1) * 8;
  const uint32_t offA = (uint32_t)((rowA * 20 + ((lane >> 4) << 2)) << 2);
  const int rowB = (lane & 7) + ((lane >> 4) << 3);
  const uint32_t offB = (uint32_t)((rowB * 20 + (((lane >> 3) & 1) << 2)) << 2);

  uint32_t aAddr[2], bAddr[4];
#pragma unroll
  for (int mt = 0; mt < 2; mt++)
    aAddr[mt] = smem_u32(&As[0][0]) + offA + (uint32_t)(((wm << 5) + (mt << 4)) * 80);
#pragma unroll
  for (int p = 0; p < 4; p++)
    bAddr[p] = smem_u32(&Bs[0][0]) + offB + (uint32_t)(((wn << 6) + (p << 4)) * 80);

  float c[2][8][4] = {};

  for (int kb = 0; kb < DM; kb += 16) {
#pragma unroll
    for (int j = 0; j < 2; j++) {
      int idx = tid + (j << 8);
      int row = idx & 127;
      int c4  = (idx >> 7) << 2;
      float4 v = *reinterpret_cast<const float4*>(&X[(size_t)(mbase + row) * DM + kb + c4]);
      v.x = tf32r(v.x); v.y = tf32r(v.y); v.z = tf32r(v.z); v.w = tf32r(v.w);
      *reinterpret_cast<float4*>(&As[row][c4]) = v;
      float4 w = *reinterpret_cast<const float4*>(&W[(size_t)(nbase + row) * DM + kb + c4]);
      w.x = tf32r(w.x); w.y = tf32r(w.y); w.z = tf32r(w.z); w.w = tf32r(w.w);
      *reinterpret_cast<float4*>(&Bs[row][c4]) = w;
    }
    __syncthreads();

#pragma unroll
    for (int kk = 0; kk < 16; kk += 8) {
      uint32_t af[2][4], bf[4][4];
#pragma unroll
      for (int mt = 0; mt < 2; mt++) ldsm4(af[mt], aAddr[mt] + (kk << 2));
#pragma unroll
      for (int p = 0; p < 4; p++) ldsm4(bf[p], bAddr[p] + (kk << 2));
#pragma unroll
      for (int mt = 0; mt < 2; mt++)
#pragma unroll
        for (int p = 0; p < 4; p++) {
          mma8(c[mt][2 * p],     af[mt], &bf[p][0]);
          mma8(c[mt][2 * p + 1], af[mt], &bf[p][2]);
        }
    }
    __syncthreads();
  }

#pragma unroll
  for (int mt = 0; mt < 2; mt++) {
    int r = mbase + (wm << 5) + (mt << 4) + g;
#pragma unroll
    for (int nt = 0; nt < 8; nt++) {
      int cc = nbase + (wn << 6) + (nt << 3) + (tig << 1);
      float2 bv = *reinterpret_cast<const float2*>(&bias[cc]);
      float o0 = c[mt][nt][0] + bv.x, o1 = c[mt][nt][1] + bv.y;
      float o2 = c[mt][nt][2] + bv.x, o3 = c[mt][nt][3] + bv.y;
      if (resid != nullptr) {
        float2 r0 = *reinterpret_cast<const float2*>(&resid[(size_t)r * DM + cc]);
        float2 r1 = *reinterpret_cast<const float2*>(&resid[(size_t)(r + 8) * DM + cc]);
        o0 += r0.x; o1 += r0.y; o2 += r1.x; o3 += r1.y;
      }
      if (round_out) {
        o0 = tf32r(o0); o1 = tf32r(o1); o2 = tf32r(o2); o3 = tf32r(o3);
      }
      float2 w0 = {o0, o1}, w1 = {o2, o3};
      *reinterpret_cast<float2*>(&out[(size_t)r * DM + cc]) = w0;
      *reinterpret_cast<float2*>(&out[(size_t)(r + 8) * DM + cc]) = w1;
    }
  }
}

// ---------------------------------------------------------------------------
// Two-sweep fused attention, TF32 mma + ldmatrix + cp.async staging.
// g_Q/g_K/g_V arrive pre-rounded to tf32. CTA = 128 q x one (b,h),
// 8 warps (4q x 2n), warp 32x32.
// Sweep 1: rowsums, K double-buffered (buf1 aliases Es), 1 barrier/tile.
// Sweep 2: normalized E -> Es; ctx mma; coalesced Es -> gmem store.
// smem (105984B): Qs[128][68] Ks[64][68] Vt[64][68] Es[128][68] red sinv
// ---------------------------------------------------------------------------
__global__ __launch_bounds__(256, 2) void attn_mma(float* __restrict__ attn_out) {
  extern __shared__ float sm[];
  float (*Qs)[68] = reinterpret_cast<float(*)[68]>(sm);
  float (*Ks)[68] = reinterpret_cast<float(*)[68]>(sm + 8704);
  float (*Vt)[68] = reinterpret_cast<float(*)[68]>(sm + 13056);
  float (*Es)[68] = reinterpret_cast<float(*)[68]>(sm + 17408);
  float (*red)[2] = reinterpret_cast<float(*)[2]>(sm + 26112);
  float* sinv = sm + 26368;

  const int tid = threadIdx.x;
  const int lane = tid & 31, wid = tid >> 5;
  const int g = lane >> 2, tig = lane & 3;
  const int wq = wid >> 1, wn = wid & 1;       // 4q x 2n warps
  const int bh = blockIdx.y;                   // h*2 + b
  const int h = bh >> 1, b = bh & 1;
  const int qbase = blockIdx.x << 7;

  const float* Qg = g_Q + (size_t)(b * SEQ + qbase) * DM + h * DKH;
  const float* Kg = g_K + (size_t)(b * SEQ) * DM + h * DKH;
  const float* Vg = g_V + (size_t)(b * SEQ) * DM + h * DKH;

  // ldmatrix per-lane offsets (bytes), stride 68 floats = 272B
  const int rowA = (lane & 7) + ((lane >> 3) & 1) * 8;
  const uint32_t offA = (uint32_t)((rowA * 68 + ((lane >> 4) << 2)) << 2);
  const int rowB = (lane & 7) + ((lane >> 4) << 3);
  const uint32_t offB = (uint32_t)((rowB * 68 + (((lane >> 3) & 1) << 2)) << 2);

  const uint32_t ksBase = smem_u32(&Ks[0][0]);
  const uint32_t esBase = smem_u32(&Es[0][0]);

  uint32_t qAddr[2], eAddr[2], vAddr[2], kOff[2];
#pragma unroll
  for (int mt = 0; mt < 2; mt++) {
    uint32_t moff = (uint32_t)(((wq << 5) + (mt << 4)) * 272);
    qAddr[mt] = smem_u32(&Qs[0][0]) + offA + moff;
    eAddr[mt] = esBase + offA + moff;
  }
#pragma unroll
  for (int p = 0; p < 2; p++) {
    uint32_t noff = (uint32_t)(((wn << 5) + (p << 4)) * 272);
    kOff[p]  = offB + noff;                  // add ksBase or esBase (buffer)
    vAddr[p] = smem_u32(&Vt[0][0]) + offB + noff;
  }

  // Stage Q via cp.async (values already tf32)
#pragma unroll
  for (int j = 0; j < 8; j++) {
    int idx = tid + (j << 8);
    int row = idx >> 4, c4 = (idx & 15) << 2;
    cpa16(smem_u32(&Qs[row][c4]), &Qg[(size_t)row * DM + c4]);
  }
  cpa_commit();

  // K tile stage (async, no conversion)
  auto stageK = [&](uint32_t dstBase, int kb) {
#pragma unroll
    for (int j = 0; j < 4; j++) {
      int idx = tid + (j << 8);
      int row = idx >> 4, c4 = (idx & 15) << 2;
      cpa16(dstBase + (uint32_t)((row * 68 + c4) << 2), &Kg[(size_t)(kb + row) * DM + c4]);
    }
  };

  // ---------------- sweep 1: rowsums (K double-buffered: Ks, Es) ----------
  stageK(ksBase, 0);
  cpa_commit();

  float rs[2][2] = {};
  for (int kt = 0; kt < 32; kt++) {
    const uint32_t curBase = (kt & 1) ? esBase : ksBase;
    const uint32_t nxtBase = (kt & 1) ? ksBase : esBase;
    cpa_wait0();
    __syncthreads();
    if (kt + 1 < 32) { stageK(nxtBase, (kt + 1) << 6); cpa_commit(); }

    float s[2][4][4] = {};
#pragma unroll
    for (int d8 = 0; d8 < 64; d8 += 8) {
      uint32_t af[2][4], bf[2][4];
#pragma unroll
      for (int mt = 0; mt < 2; mt++) ldsm4(af[mt], qAddr[mt] + (d8 << 2));
#pragma unroll
      for (int p = 0; p < 2; p++) ldsm4(bf[p], curBase + kOff[p] + (d8 << 2));
#pragma unroll
      for (int mt = 0; mt < 2; mt++)
#pragma unroll
        for (int p = 0; p < 2; p++) {
          mma8(s[mt][2 * p],     af[mt], &bf[p][0]);
          mma8(s[mt][2 * p + 1], af[mt], &bf[p][2]);
        }
    }
#pragma unroll
    for (int mt = 0; mt < 2; mt++)
#pragma unroll
      for (int nt = 0; nt < 4; nt++) {
        rs[mt][0] += __expf(s[mt][nt][0] * INV_TEMP) + __expf(s[mt][nt][1] * INV_TEMP);
        rs[mt][1] += __expf(s[mt][nt][2] * INV_TEMP) + __expf(s[mt][nt][3] * INV_TEMP);
      }
  }
  __syncthreads();

  // Reduce rowsums across tig lanes, then across the 2 n-warps
#pragma unroll
  for (int mt = 0; mt < 2; mt++)
#pragma unroll
    for (int u = 0; u < 2; u++) {
      rs[mt][u] += __shfl_xor_sync(0xffffffffu, rs[mt][u], 1);
      rs[mt][u] += __shfl_xor_sync(0xffffffffu, rs[mt][u], 2);
    }
  if (tig == 0) {
#pragma unroll
    for (int mt = 0; mt < 2; mt++)
#pragma unroll
      for (int u = 0; u < 2; u++)
        red[(wq << 5) + (mt << 4) + (u << 3) + g][wn] = rs[mt][u];
  }
  __syncthreads();
  if (tid < 128) sinv[tid] = 1.0f / (red[tid][0] + red[tid][1]);
  __syncthreads();

  float inv[2][2];
#pragma unroll
  for (int mt = 0; mt < 2; mt++) {
    inv[mt][0] = sinv[(wq << 5) + (mt << 4) + g];
    inv[mt][1] = sinv[(wq << 5) + (mt << 4) + 8 + g];
  }
  __syncthreads();

  // ---------------- sweep 2: normalized attn + context ----------------
  float cx[2][4][4] = {};
  for (int kb = 0; kb < SEQ; kb += 64) {
    // K async (single buffer), its latency hides behind the manual V stage
    stageK(ksBase, kb);
    cpa_commit();
    // V transposed [dv][key] (values already tf32 -> plain copy)
#pragma unroll
    for (int j = 0; j < 4; j++) {
      int idx = tid + (j << 8);
      int key = idx & 63, c4 = (idx >> 6) << 2;
      float4 v = *reinterpret_cast<const float4*>(&Vg[(size_t)(kb + key) * DM + c4]);
      Vt[c4 + 0][key] = v.x;
      Vt[c4 + 1][key] = v.y;
      Vt[c4 + 2][key] = v.z;
      Vt[c4 + 3][key] = v.w;
    }
    cpa_wait0();
    __syncthreads();

    // Scores
    float s[2][4][4] = {};
#pragma unroll
    for (int d8 = 0; d8 < 64; d8 += 8) {
      uint32_t af[2][4], bf[2][4];
#pragma unroll
      for (int mt = 0; mt < 2; mt++) ldsm4(af[mt], qAddr[mt] + (d8 << 2));
#pragma unroll
      for (int p = 0; p < 2; p++) ldsm4(bf[p], ksBase + kOff[p] + (d8 << 2));
#pragma unroll
      for (int mt = 0; mt < 2; mt++)
#pragma unroll
        for (int p = 0; p < 2; p++) {
          mma8(s[mt][2 * p],     af[mt], &bf[p][0]);
          mma8(s[mt][2 * p + 1], af[mt], &bf[p][2]);
        }
    }

    // exp, normalize, tf32-round -> Es only
#pragma unroll
    for (int mt = 0; mt < 2; mt++) {
      int r0 = (wq << 5) + (mt << 4) + g;
#pragma unroll
      for (int nt = 0; nt < 4; nt++) {
        int c0 = (wn << 5) + (nt << 3) + (tig << 1);
        float e0 = __expf(s[mt][nt][0] * INV_TEMP) * inv[mt][0];
        float e1 = __expf(s[mt][nt][1] * INV_TEMP) * inv[mt][0];
        float e2 = __expf(s[mt][nt][2] * INV_TEMP) * inv[mt][1];
        float e3 = __expf(s[mt][nt][3] * INV_TEMP) * inv[mt][1];
        float2 t0 = {tf32r(e0), tf32r(e1)}, t1 = {tf32r(e2), tf32r(e3)};
        *reinterpret_cast<float2*>(&Es[r0][c0]) = t0;
        *reinterpret_cast<float2*>(&Es[r0 + 8][c0]) = t1;
      }
    }
    __syncthreads();

    // ctx += E @ V
#pragma unroll
    for (int k8 = 0; k8 < 64; k8 += 8) {
      uint32_t af[2][4], bf[2][4];
#pragma unroll
      for (int mt = 0; mt < 2; mt++) ldsm4(af[mt], eAddr[mt] + (k8 << 2));
#pragma unroll
      for (int p = 0; p < 2; p++) ldsm4(bf[p], vAddr[p] + (k8 << 2));
#pragma unroll
      for (int mt = 0; mt < 2; mt++)
#pragma unroll
        for (int p = 0; p < 2; p++) {
          mma8(cx[mt][2 * p],     af[mt], &bf[p][0]);
          mma8(cx[mt][2 * p + 1], af[mt], &bf[p][2]);
        }
    }

    // Coalesced attn store from Es (reads only; next write is after top barrier)
#pragma unroll
    for (int j = 0; j < 8; j++) {
      int idx = tid + (j << 8);
      int row = idx >> 4, c4 = (idx & 15) << 2;
      float4 e = *reinterpret_cast<const float4*>(&Es[row][c4]);
      size_t go = ((size_t)bh * SEQ + qbase + row) * SEQ + kb + c4;
      *reinterpret_cast<float4*>(&attn_out[go]) = e;
    }
    __syncthreads();
  }

  // Write context (merged heads), already normalized
#pragma unroll
  for (int mt = 0; mt < 2; mt++) {
    int r = b * SEQ + qbase + (wq << 5) + (mt << 4) + g;
#pragma unroll
    for (int nt = 0; nt < 4; nt++) {
      int cc = h * DKH + (wn << 5) + (nt << 3) + (tig << 1);
      float2 w0 = {cx[mt][nt][0], cx[mt][nt][1]};
      float2 w1 = {cx[mt][nt][2], cx[mt][nt][3]};
      *reinterpret_cast<float2*>(&g_ctx[(size_t)r * DM + cc]) = w0;
      *reinterpret_cast<float2*>(&g_ctx[(size_t)(r + 8) * DM + cc]) = w1;
    }
  }
}

// ---------------------------------------------------------------------------
// LayerNorm over last dim (512), one block per row.
// ---------------------------------------------------------------------------
__global__ __launch_bounds__(256) void ln_kernel(
    const float* __restrict__ gamma, const float* __restrict__ beta,
    float* __restrict__ y) {
  __shared__ float warp_s[8], warp_q[8];
  __shared__ float s_mu, s_rstd;
  const int row = blockIdx.x;
  const int tid = threadIdx.x;
  const float* x = g_x + (size_t)row * DM;

  float v0 = x[tid], v1 = x[tid + 256];
  float s = v0 + v1;
  float q = v0 * v0 + v1 * v1;
#pragma unroll
  for (int o = 16; o > 0; o >>= 1) {
    s += __shfl_xor_sync(0xffffffffu, s, o);
    q += __shfl_xor_sync(0xffffffffu, q, o);
  }
  if ((tid & 31) == 0) { warp_s[tid >> 5] = s; warp_q[tid >> 5] = q; }
  __syncthreads();
  if (tid == 0) {
    float ss = 0.f, qq = 0.f;
#pragma unroll
    for (int i = 0; i < 8; i++) { ss += warp_s[i]; qq += warp_q[i]; }
    float mu = ss * (1.0f / DM);
    float var = qq * (1.0f / DM) - mu * mu;
    s_mu = mu;
    s_rstd = rsqrtf(var + LN_EPS);
  }
  __syncthreads();
  float mu = s_mu, r = s_rstd;
  y[(size_t)row * DM + tid]       = (v0 - mu) * r * gamma[tid] + beta[tid];
  y[(size_t)row * DM + tid + 256] = (v1 - mu) * r * gamma[tid + 256] + beta[tid + 256];
}

// ---------------------------------------------------------------------------
extern "C" void kernel_launch(void* const* d_in, const int* in_sizes, int n_in,
                              void* d_out, int out_size) {
  const float* q     = (const float*)d_in[0];
  const float* k     = (const float*)d_in[1];
  const float* v     = (const float*)d_in[2];
  const float* Wq    = (const float*)d_in[3];
  const float* bq    = (const float*)d_in[4];
  const float* Wk    = (const float*)d_in[5];
  const float* bk    = (const float*)d_in[6];
  const float* Wv    = (const float*)d_in[7];
  const float* bv    = (const float*)d_in[8];
  const float* Wfc   = (const float*)d_in[9];
  const float* bfc   = (const float*)d_in[10];
  const float* gamma = (const float*)d_in[11];
  const float* beta  = (const float*)d_in[12];

  float* out = (float*)d_out;                       // y: [2,2048,512]
  float* attn_out = out + (size_t)MM * DM;          // attn: [16,2048,2048]

  float *gQ, *gK, *gV, *gctx, *gx;
  cudaGetSymbolAddress((void**)&gQ, g_Q);
  cudaGetSymbolAddress((void**)&gK, g_K);
  cudaGetSymbolAddress((void**)&gV, g_V);
  cudaGetSymbolAddress((void**)&gctx, g_ctx);
  cudaGetSymbolAddress((void**)&gx, g_x);

  cudaFuncSetAttribute(attn_mma, cudaFuncAttributeMaxDynamicSharedMemorySize, 105984);

  dim3 gg(DM / 128, MM / 128);     // (4, 32) = 128 CTAs
  gemm_mma<<<gg, 256>>>(q, Wq, bq, nullptr, gQ, 1);
  gemm_mma<<<gg, 256>>>(k, Wk, bk, nullptr, gK, 1);
  gemm_mma<<<gg, 256>>>(v, Wv, bv, nullptr, gV, 1);

  dim3 ga(SEQ / 128, NH * B2);     // (16, 16)
  attn_mma<<<ga, 256, 105984>>>(attn_out);

  gemm_mma<<<gg, 256>>>(gctx, Wfc, bfc, q, gx, 0);
  ln_kernel<<<MM, 256>>>(gamma, beta, out);
}

// round 11
// speedup vs baseline: 1.4727x; 1.0995x over previous
#include <cuda_runtime.h>
#include <cstdint>
#include <cstddef>

namespace {
constexpr int B2  = 2;
constexpr int SEQ = 2048;
constexpr int DM  = 512;
constexpr int NH  = 8;
constexpr int DKH = 64;
constexpr int MM  = B2 * SEQ;              // 4096
constexpr float INV_TEMP = 0.04419417382415922f;  // 1/sqrt(512)
constexpr float LN_EPS = 1e-5f;
}

// Scratch (device globals — allocations are forbidden)
__device__ float g_Q[MM * DM];
__device__ float g_K[MM * DM];
__device__ float g_V[MM * DM];
__device__ float g_Vt[NH * B2 * DKH * SEQ];   // [bh][dv][seq], bh = h*2+b
__device__ float g_ctx[MM * DM];
__device__ float g_x[MM * DM];

__device__ __forceinline__ float tf32r(float x) {
  uint32_t o;
  asm("cvt.rna.tf32.f32 %0, %1;" : "=r"(o) : "f"(x));
  return __uint_as_float(o);
}

__device__ __forceinline__ void mma8(float* c, const uint32_t* a, const uint32_t* b) {
  asm volatile(
      "mma.sync.aligned.m16n8k8.row.col.f32.tf32.tf32.f32 "
      "{%0,%1,%2,%3}, {%4,%5,%6,%7}, {%8,%9}, {%0,%1,%2,%3};"
      : "+f"(c[0]), "+f"(c[1]), "+f"(c[2]), "+f"(c[3])
      : "r"(a[0]), "r"(a[1]), "r"(a[2]), "r"(a[3]), "r"(b[0]), "r"(b[1]));
}

__device__ __forceinline__ void ldsm4(uint32_t* r, uint32_t addr) {
  asm volatile("ldmatrix.sync.aligned.m8n8.x4.shared.b16 {%0,%1,%2,%3}, [%4];"
               : "=r"(r[0]), "=r"(r[1]), "=r"(r[2]), "=r"(r[3]) : "r"(addr));
}

__device__ __forceinline__ uint32_t smem_u32(const void* p) {
  return (uint32_t)__cvta_generic_to_shared(p);
}

__device__ __forceinline__ void cpa16(uint32_t dst, const void* src) {
  asm volatile("cp.async.cg.shared.global [%0], [%1], 16;" :: "r"(dst), "l"(src));
}
__device__ __forceinline__ void cpa_commit() {
  asm volatile("cp.async.commit_group;");
}
__device__ __forceinline__ void cpa_wait0() {
  asm volatile("cp.async.wait_group 0;");
}
__device__ __forceinline__ void cpa_wait1() {
  asm volatile("cp.async.wait_group 1;");
}

// ---------------------------------------------------------------------------
// Dense GEMM, 1xTF32 + ldmatrix: out = X @ W^T + bias (+resid).
// CTA 128x128, 8 warps (4m x 2n), warp 32x64, K-step 16. smem stride 20.
// ---------------------------------------------------------------------------
__global__ __launch_bounds__(256) void gemm_mma(
    const float* __restrict__ X, const float* __restrict__ W,
    const float* __restrict__ bias, const float* __restrict__ resid,
    float* __restrict__ out, int round_out) {
  __shared__ float As[128][20];
  __shared__ float Bs[128][20];
  const int tid = threadIdx.x;
  const int lane = tid & 31, wid = tid >> 5;
  const int g = lane >> 2, tig = lane & 3;
  const int wm = wid & 3, wn = wid >> 2;
  const int mbase = blockIdx.y << 7;
  const int nbase = blockIdx.x << 7;

  const int rowA = (lane & 7) + ((lane >> 3) & 1) * 8;
  const uint32_t offA = (uint32_t)((rowA * 20 + ((lane >> 4) << 2)) << 2);
  const int rowB = (lane & 7) + ((lane >> 4) << 3);
  const uint32_t offB = (uint32_t)((rowB * 20 + (((lane >> 3) & 1) << 2)) << 2);

  uint32_t aAddr[2], bAddr[4];
#pragma unroll
  for (int mt = 0; mt < 2; mt++)
    aAddr[mt] = smem_u32(&As[0][0]) + offA + (uint32_t)(((wm << 5) + (mt << 4)) * 80);
#pragma unroll
  for (int p = 0; p < 4; p++)
    bAddr[p] = smem_u32(&Bs[0][0]) + offB + (uint32_t)(((wn << 6) + (p << 4)) * 80);

  float c[2][8][4] = {};

  for (int kb = 0; kb < DM; kb += 16) {
#pragma unroll
    for (int j = 0; j < 2; j++) {
      int idx = tid + (j << 8);
      int row = idx & 127;
      int c4  = (idx >> 7) << 2;
      float4 v = *reinterpret_cast<const float4*>(&X[(size_t)(mbase + row) * DM + kb + c4]);
      v.x = tf32r(v.x); v.y = tf32r(v.y); v.z = tf32r(v.z); v.w = tf32r(v.w);
      *reinterpret_cast<float4*>(&As[row][c4]) = v;
      float4 w = *reinterpret_cast<const float4*>(&W[(size_t)(nbase + row) * DM + kb + c4]);
      w.x = tf32r(w.x); w.y = tf32r(w.y); w.z = tf32r(w.z); w.w = tf32r(w.w);
      *reinterpret_cast<float4*>(&Bs[row][c4]) = w;
    }
    __syncthreads();

#pragma unroll
    for (int kk = 0; kk < 16; kk += 8) {
      uint32_t af[2][4], bf[4][4];
#pragma unroll
      for (int mt = 0; mt < 2; mt++) ldsm4(af[mt], aAddr[mt] + (kk << 2));
#pragma unroll
      for (int p = 0; p < 4; p++) ldsm4(bf[p], bAddr[p] + (kk << 2));
#pragma unroll
      for (int mt = 0; mt < 2; mt++)
#pragma unroll
        for (int p = 0; p < 4; p++) {
          mma8(c[mt][2 * p],     af[mt], &bf[p][0]);
          mma8(c[mt][2 * p + 1], af[mt], &bf[p][2]);
        }
    }
    __syncthreads();
  }

#pragma unroll
  for (int mt = 0; mt < 2; mt++) {
    int r = mbase + (wm << 5) + (mt << 4) + g;
#pragma unroll
    for (int nt = 0; nt < 8; nt++) {
      int cc = nbase + (wn << 6) + (nt << 3) + (tig << 1);
      float2 bv = *reinterpret_cast<const float2*>(&bias[cc]);
      float o0 = c[mt][nt][0] + bv.x, o1 = c[mt][nt][1] + bv.y;
      float o2 = c[mt][nt][2] + bv.x, o3 = c[mt][nt][3] + bv.y;
      if (resid != nullptr) {
        float2 r0 = *reinterpret_cast<const float2*>(&resid[(size_t)r * DM + cc]);
        float2 r1 = *reinterpret_cast<const float2*>(&resid[(size_t)(r + 8) * DM + cc]);
        o0 += r0.x; o1 += r0.y; o2 += r1.x; o3 += r1.y;
      }
      if (round_out) {
        o0 = tf32r(o0); o1 = tf32r(o1); o2 = tf32r(o2); o3 = tf32r(o3);
      }
      float2 w0 = {o0, o1}, w1 = {o2, o3};
      *reinterpret_cast<float2*>(&out[(size_t)r * DM + cc]) = w0;
      *reinterpret_cast<float2*>(&out[(size_t)(r + 8) * DM + cc]) = w1;
    }
  }
}

// ---------------------------------------------------------------------------
// V transpose: g_V[b*SEQ+s][h*64+dv] -> g_Vt[(h*2+b)*64+dv][s].
// Tiled 32x32 via smem. Grid (SEQ/32, DM/32, B2), block (32, 8).
// ---------------------------------------------------------------------------
__global__ __launch_bounds__(256) void vtrans() {
  __shared__ float t[32][33];
  const int s0  = blockIdx.x << 5;
  const int dvt = blockIdx.y;               // over DM/32 = 16
  const int b   = blockIdx.z;
  const int h   = dvt >> 1;
  const int dv0 = (dvt & 1) << 5;
  const int tx = threadIdx.x, ty = threadIdx.y;
#pragma unroll
  for (int k = 0; k < 32; k += 8)
    t[ty + k][tx] = g_V[(size_t)(b * SEQ + s0 + ty + k) * DM + (dvt << 5) + tx];
  __syncthreads();
  const int bh = h * 2 + b;
#pragma unroll
  for (int k = 0; k < 32; k += 8)
    g_Vt[((size_t)bh * DKH + dv0 + ty + k) * SEQ + s0 + tx] = t[tx][ty + k];
}

// ---------------------------------------------------------------------------
// Two-sweep fused attention, TF32 mma + ldmatrix + fully-async staging.
// Sweep 1: rowsums, K double-buffered (buf1 aliases Es), 1 barrier/tile.
// Sweep 2: K and V(pre-transposed) via pipelined cp.async groups.
// smem (105984B): Qs[128][68] Ks[64][68] Vt[64][68] Es[128][68] red sinv
// ---------------------------------------------------------------------------
__global__ __launch_bounds__(256, 2) void attn_mma(float* __restrict__ attn_out) {
  extern __shared__ float sm[];
  float (*Qs)[68] = reinterpret_cast<float(*)[68]>(sm);
  float (*Ks)[68] = reinterpret_cast<float(*)[68]>(sm + 8704);
  float (*Vt)[68] = reinterpret_cast<float(*)[68]>(sm + 13056);
  float (*Es)[68] = reinterpret_cast<float(*)[68]>(sm + 17408);
  float (*red)[2] = reinterpret_cast<float(*)[2]>(sm + 26112);
  float* sinv = sm + 26368;

  const int tid = threadIdx.x;
  const int lane = tid & 31, wid = tid >> 5;
  const int g = lane >> 2, tig = lane & 3;
  const int wq = wid >> 1, wn = wid & 1;       // 4q x 2n warps
  const int bh = blockIdx.y;                   // h*2 + b
  const int h = bh >> 1, b = bh & 1;
  const int qbase = blockIdx.x << 7;

  const float* Qg  = g_Q + (size_t)(b * SEQ + qbase) * DM + h * DKH;
  const float* Kg  = g_K + (size_t)(b * SEQ) * DM + h * DKH;
  const float* VTg = g_Vt + (size_t)bh * DKH * SEQ;   // [64][2048]

  const int rowA = (lane & 7) + ((lane >> 3) & 1) * 8;
  const uint32_t offA = (uint32_t)((rowA * 68 + ((lane >> 4) << 2)) << 2);
  const int rowB = (lane & 7) + ((lane >> 4) << 3);
  const uint32_t offB = (uint32_t)((rowB * 68 + (((lane >> 3) & 1) << 2)) << 2);

  const uint32_t ksBase = smem_u32(&Ks[0][0]);
  const uint32_t vtBase = smem_u32(&Vt[0][0]);
  const uint32_t esBase = smem_u32(&Es[0][0]);

  uint32_t qAddr[2], eAddr[2], vAddr[2], kOff[2];
#pragma unroll
  for (int mt = 0; mt < 2; mt++) {
    uint32_t moff = (uint32_t)(((wq << 5) + (mt << 4)) * 272);
    qAddr[mt] = smem_u32(&Qs[0][0]) + offA + moff;
    eAddr[mt] = esBase + offA + moff;
  }
#pragma unroll
  for (int p = 0; p < 2; p++) {
    uint32_t noff = (uint32_t)(((wn << 5) + (p << 4)) * 272);
    kOff[p]  = offB + noff;
    vAddr[p] = vtBase + offB + noff;
  }

  // Stage Q via cp.async (values already tf32)
#pragma unroll
  for (int j = 0; j < 8; j++) {
    int idx = tid + (j << 8);
    int row = idx >> 4, c4 = (idx & 15) << 2;
    cpa16(smem_u32(&Qs[row][c4]), &Qg[(size_t)row * DM + c4]);
  }
  cpa_commit();

  auto stageK = [&](uint32_t dstBase, int kb) {
#pragma unroll
    for (int j = 0; j < 4; j++) {
      int idx = tid + (j << 8);
      int row = idx >> 4, c4 = (idx & 15) << 2;
      cpa16(dstBase + (uint32_t)((row * 68 + c4) << 2), &Kg[(size_t)(kb + row) * DM + c4]);
    }
  };
  // V tile: 64 dv x 64 keys = 1024 float4 -> 4 cp.async per thread.
  auto stageV = [&](int kb) {
#pragma unroll
    for (int j = 0; j < 4; j++) {
      int idx = tid + (j << 8);
      int dv = idx >> 4, c4 = (idx & 15) << 2;
      cpa16(vtBase + (uint32_t)((dv * 68 + c4) << 2), &VTg[(size_t)dv * SEQ + kb + c4]);
    }
  };

  // ---------------- sweep 1: rowsums (K double-buffered: Ks, Es) ----------
  stageK(ksBase, 0);
  cpa_commit();

  float rs[2][2] = {};
  for (int kt = 0; kt < 32; kt++) {
    const uint32_t curBase = (kt & 1) ? esBase : ksBase;
    const uint32_t nxtBase = (kt & 1) ? ksBase : esBase;
    cpa_wait0();
    __syncthreads();
    if (kt + 1 < 32) { stageK(nxtBase, (kt + 1) << 6); cpa_commit(); }

    float s[2][4][4] = {};
#pragma unroll
    for (int d8 = 0; d8 < 64; d8 += 8) {
      uint32_t af[2][4], bf[2][4];
#pragma unroll
      for (int mt = 0; mt < 2; mt++) ldsm4(af[mt], qAddr[mt] + (d8 << 2));
#pragma unroll
      for (int p = 0; p < 2; p++) ldsm4(bf[p], curBase + kOff[p] + (d8 << 2));
#pragma unroll
      for (int mt = 0; mt < 2; mt++)
#pragma unroll
        for (int p = 0; p < 2; p++) {
          mma8(s[mt][2 * p],     af[mt], &bf[p][0]);
          mma8(s[mt][2 * p + 1], af[mt], &bf[p][2]);
        }
    }
#pragma unroll
    for (int mt = 0; mt < 2; mt++)
#pragma unroll
      for (int nt = 0; nt < 4; nt++) {
        rs[mt][0] += __expf(s[mt][nt][0] * INV_TEMP) + __expf(s[mt][nt][1] * INV_TEMP);
        rs[mt][1] += __expf(s[mt][nt][2] * INV_TEMP) + __expf(s[mt][nt][3] * INV_TEMP);
      }
  }
  __syncthreads();

#pragma unroll
  for (int mt = 0; mt < 2; mt++)
#pragma unroll
    for (int u = 0; u < 2; u++) {
      rs[mt][u] += __shfl_xor_sync(0xffffffffu, rs[mt][u], 1);
      rs[mt][u] += __shfl_xor_sync(0xffffffffu, rs[mt][u], 2);
    }
  if (tig == 0) {
#pragma unroll
    for (int mt = 0; mt < 2; mt++)
#pragma unroll
      for (int u = 0; u < 2; u++)
        red[(wq << 5) + (mt << 4) + (u << 3) + g][wn] = rs[mt][u];
  }
  __syncthreads();
  if (tid < 128) sinv[tid] = 1.0f / (red[tid][0] + red[tid][1]);
  __syncthreads();

  float inv[2][2];
#pragma unroll
  for (int mt = 0; mt < 2; mt++) {
    inv[mt][0] = sinv[(wq << 5) + (mt << 4) + g];
    inv[mt][1] = sinv[(wq << 5) + (mt << 4) + 8 + g];
  }
  __syncthreads();

  // ---------------- sweep 2: pipelined normalized attn + context ----------
  stageK(ksBase, 0); cpa_commit();
  stageV(0);         cpa_commit();

  float cx[2][4][4] = {};
  for (int kt = 0; kt < 32; kt++) {
    const int kb = kt << 6;
    cpa_wait1();                 // K(kt) complete (V(kt) may still fly)
    __syncthreads();

    // Scores
    float s[2][4][4] = {};
#pragma unroll
    for (int d8 = 0; d8 < 64; d8 += 8) {
      uint32_t af[2][4], bf[2][4];
#pragma unroll
      for (int mt = 0; mt < 2; mt++) ldsm4(af[mt], qAddr[mt] + (d8 << 2));
#pragma unroll
      for (int p = 0; p < 2; p++) ldsm4(bf[p], ksBase + kOff[p] + (d8 << 2));
#pragma unroll
      for (int mt = 0; mt < 2; mt++)
#pragma unroll
        for (int p = 0; p < 2; p++) {
          mma8(s[mt][2 * p],     af[mt], &bf[p][0]);
          mma8(s[mt][2 * p + 1], af[mt], &bf[p][2]);
        }
    }

    // exp, normalize, tf32-round -> Es
#pragma unroll
    for (int mt = 0; mt < 2; mt++) {
      int r0 = (wq << 5) + (mt << 4) + g;
#pragma unroll
      for (int nt = 0; nt < 4; nt++) {
        int c0 = (wn << 5) + (nt << 3) + (tig << 1);
        float e0 = __expf(s[mt][nt][0] * INV_TEMP) * inv[mt][0];
        float e1 = __expf(s[mt][nt][1] * INV_TEMP) * inv[mt][0];
        float e2 = __expf(s[mt][nt][2] * INV_TEMP) * inv[mt][1];
        float e3 = __expf(s[mt][nt][3] * INV_TEMP) * inv[mt][1];
        float2 t0 = {tf32r(e0), tf32r(e1)}, t1 = {tf32r(e2), tf32r(e3)};
        *reinterpret_cast<float2*>(&Es[r0][c0]) = t0;
        *reinterpret_cast<float2*>(&Es[r0 + 8][c0]) = t1;
      }
    }
    cpa_wait0();                 // V(kt) complete
    __syncthreads();
    if (kt + 1 < 32) { stageK(ksBase, (kt + 1) << 6); cpa_commit(); }  // Ks free

    // ctx += E @ V
#pragma unroll
    for (int k8 = 0; k8 < 64; k8 += 8) {
      uint32_t af[2][4], bf[2][4];
#pragma unroll
      for (int mt = 0; mt < 2; mt++) ldsm4(af[mt], eAddr[mt] + (k8 << 2));
#pragma unroll
      for (int p = 0; p < 2; p++) ldsm4(bf[p], vAddr[p] + (k8 << 2));
#pragma unroll
      for (int mt = 0; mt < 2; mt++)
#pragma unroll
        for (int p = 0; p < 2; p++) {
          mma8(cx[mt][2 * p],     af[mt], &bf[p][0]);
          mma8(cx[mt][2 * p + 1], af[mt], &bf[p][2]);
        }
    }

    // Coalesced attn store from Es
#pragma unroll
    for (int j = 0; j < 8; j++) {
      int idx = tid + (j << 8);
      int row = idx >> 4, c4 = (idx & 15) << 2;
      float4 e = *reinterpret_cast<const float4*>(&Es[row][c4]);
      size_t go = ((size_t)bh * SEQ + qbase + row) * SEQ + kb + c4;
      *reinterpret_cast<float4*>(&attn_out[go]) = e;
    }
    __syncthreads();
    if (kt + 1 < 32) { stageV((kt + 1) << 6); cpa_commit(); }          // Vt free
  }

  // Write context (merged heads), already normalized
#pragma unroll
  for (int mt = 0; mt < 2; mt++) {
    int r = b * SEQ + qbase + (wq << 5) + (mt << 4) + g;
#pragma unroll
    for (int nt = 0; nt < 4; nt++) {
      int cc = h * DKH + (wn << 5) + (nt << 3) + (tig << 1);
      float2 w0 = {cx[mt][nt][0], cx[mt][nt][1]};
      float2 w1 = {cx[mt][nt][2], cx[mt][nt][3]};
      *reinterpret_cast<float2*>(&g_ctx[(size_t)r * DM + cc]) = w0;
      *reinterpret_cast<float2*>(&g_ctx[(size_t)(r + 8) * DM + cc]) = w1;
    }
  }
}

// ---------------------------------------------------------------------------
// LayerNorm over last dim (512), one block per row.
// ---------------------------------------------------------------------------
__global__ __launch_bounds__(256) void ln_kernel(
    const float* __restrict__ gamma, const float* __restrict__ beta,
    float* __restrict__ y) {
  __shared__ float warp_s[8], warp_q[8];
  __shared__ float s_mu, s_rstd;
  const int row = blockIdx.x;
  const int tid = threadIdx.x;
  const float* x = g_x + (size_t)row * DM;

  float v0 = x[tid], v1 = x[tid + 256];
  float s = v0 + v1;
  float q = v0 * v0 + v1 * v1;
#pragma unroll
  for (int o = 16; o > 0; o >>= 1) {
    s += __shfl_xor_sync(0xffffffffu, s, o);
    q += __shfl_xor_sync(0xffffffffu, q, o);
  }
  if ((tid & 31) == 0) { warp_s[tid >> 5] = s; warp_q[tid >> 5] = q; }
  __syncthreads();
  if (tid == 0) {
    float ss = 0.f, qq = 0.f;
#pragma unroll
    for (int i = 0; i < 8; i++) { ss += warp_s[i]; qq += warp_q[i]; }
    float mu = ss * (1.0f / DM);
    float var = qq * (1.0f / DM) - mu * mu;
    s_mu = mu;
    s_rstd = rsqrtf(var + LN_EPS);
  }
  __syncthreads();
  float mu = s_mu, r = s_rstd;
  y[(size_t)row * DM + tid]       = (v0 - mu) * r * gamma[tid] + beta[tid];
  y[(size_t)row * DM + tid + 256] = (v1 - mu) * r * gamma[tid + 256] + beta[tid + 256];
}

// ---------------------------------------------------------------------------
extern "C" void kernel_launch(void* const* d_in, const int* in_sizes, int n_in,
                              void* d_out, int out_size) {
  const float* q     = (const float*)d_in[0];
  const float* k     = (const float*)d_in[1];
  const float* v     = (const float*)d_in[2];
  const float* Wq    = (const float*)d_in[3];
  const float* bq    = (const float*)d_in[4];
  const float* Wk    = (const float*)d_in[5];
  const float* bk    = (const float*)d_in[6];
  const float* Wv    = (const float*)d_in[7];
  const float* bv    = (const float*)d_in[8];
  const float* Wfc   = (const float*)d_in[9];
  const float* bfc   = (const float*)d_in[10];
  const float* gamma = (const float*)d_in[11];
  const float* beta  = (const float*)d_in[12];

  float* out = (float*)d_out;                       // y: [2,2048,512]
  float* attn_out = out + (size_t)MM * DM;          // attn: [16,2048,2048]

  float *gQ, *gK, *gV, *gctx, *gx;
  cudaGetSymbolAddress((void**)&gQ, g_Q);
  cudaGetSymbolAddress((void**)&gK, g_K);
  cudaGetSymbolAddress((void**)&gV, g_V);
  cudaGetSymbolAddress((void**)&gctx, g_ctx);
  cudaGetSymbolAddress((void**)&gx, g_x);

  cudaFuncSetAttribute(attn_mma, cudaFuncAttributeMaxDynamicSharedMemorySize, 105984);

  dim3 gg(DM / 128, MM / 128);     // (4, 32) = 128 CTAs
  gemm_mma<<<gg, 256>>>(q, Wq, bq, nullptr, gQ, 1);
  gemm_mma<<<gg, 256>>>(k, Wk, bk, nullptr, gK, 1);
  gemm_mma<<<gg, 256>>>(v, Wv, bv, nullptr, gV, 1);

  dim3 gt(SEQ / 32, DM / 32, B2);  // (64, 16, 2)
  vtrans<<<gt, dim3(32, 8)>>>();

  dim3 ga(SEQ / 128, NH * B2);     // (16, 16)
  attn_mma<<<ga, 256, 105984>>>(attn_out);

  gemm_mma<<<gg, 256>>>(gctx, Wfc, bfc, q, gx, 0);
  ln_kernel<<<MM, 256>>>(gamma, beta, out);
}

// round 12
// speedup vs baseline: 1.7123x; 1.1627x over previous
#include <cuda_runtime.h>
#include <cstdint>
#include <cstddef>

namespace {
constexpr int B2  = 2;
constexpr int SEQ = 2048;
constexpr int DM  = 512;
constexpr int NH  = 8;
constexpr int DKH = 64;
constexpr int MM  = B2 * SEQ;              // 4096
constexpr float INV_TEMP = 0.04419417382415922f;  // 1/sqrt(512)
constexpr float LN_EPS = 1e-5f;
}

// Scratch (device globals — allocations are forbidden)
__device__ float g_Q[MM * DM];
__device__ float g_K[MM * DM];
__device__ float g_V[MM * DM];
__device__ float g_Vt[NH * B2 * DKH * SEQ];   // [bh][dv][seq], bh = h*2+b
__device__ float g_ctx[MM * DM];
__device__ float g_x[MM * DM];
__device__ float g_qr[MM * DM];               // tf32-rounded inputs
__device__ float g_kr[MM * DM];
__device__ float g_vr[MM * DM];
__device__ float g_wq[DM * DM];               // tf32-rounded weights
__device__ float g_wk[DM * DM];
__device__ float g_wv[DM * DM];
__device__ float g_wfc[DM * DM];

__device__ __forceinline__ float tf32r(float x) {
  uint32_t o;
  asm("cvt.rna.tf32.f32 %0, %1;" : "=r"(o) : "f"(x));
  return __uint_as_float(o);
}

__device__ __forceinline__ void mma8(float* c, const uint32_t* a, const uint32_t* b) {
  asm volatile(
      "mma.sync.aligned.m16n8k8.row.col.f32.tf32.tf32.f32 "
      "{%0,%1,%2,%3}, {%4,%5,%6,%7}, {%8,%9}, {%0,%1,%2,%3};"
      : "+f"(c[0]), "+f"(c[1]), "+f"(c[2]), "+f"(c[3])
      : "r"(a[0]), "r"(a[1]), "r"(a[2]), "r"(a[3]), "r"(b[0]), "r"(b[1]));
}

__device__ __forceinline__ void ldsm4(uint32_t* r, uint32_t addr) {
  asm volatile("ldmatrix.sync.aligned.m8n8.x4.shared.b16 {%0,%1,%2,%3}, [%4];"
               : "=r"(r[0]), "=r"(r[1]), "=r"(r[2]), "=r"(r[3]) : "r"(addr));
}

__device__ __forceinline__ uint32_t smem_u32(const void* p) {
  return (uint32_t)__cvta_generic_to_shared(p);
}

__device__ __forceinline__ void cpa16(uint32_t dst, const void* src) {
  asm volatile("cp.async.cg.shared.global [%0], [%1], 16;" :: "r"(dst), "l"(src));
}
__device__ __forceinline__ void cpa_commit() {
  asm volatile("cp.async.commit_group;");
}
__device__ __forceinline__ void cpa_wait0() {
  asm volatile("cp.async.wait_group 0;");
}
__device__ __forceinline__ void cpa_wait1() {
  asm volatile("cp.async.wait_group 1;");
}

// ---------------------------------------------------------------------------
// Elementwise tf32 rounding: dst = rna(src). One float4 per thread.
// ---------------------------------------------------------------------------
__global__ __launch_bounds__(256) void round_tf32(
    const float* __restrict__ src, float* __restrict__ dst) {
  size_t i = (size_t)blockIdx.x * 256 + threadIdx.x;
  float4 v = reinterpret_cast<const float4*>(src)[i];
  v.x = tf32r(v.x); v.y = tf32r(v.y); v.z = tf32r(v.z); v.w = tf32r(v.w);
  reinterpret_cast<float4*>(dst)[i] = v;
}

// ---------------------------------------------------------------------------
// Dense GEMM, 1xTF32, cp.async double-buffered: out = X @ W^T + bias (+resid).
// X, W pre-rounded to tf32. CTA 128x128, 8 warps (4m x 2n), warp 32x64,
// K-step 16, 1 barrier per K-iter. Dynamic smem 81920B: 2 x (As+Bs), stride 20.
// ---------------------------------------------------------------------------
__global__ __launch_bounds__(256) void gemm_mma(
    const float* __restrict__ X, const float* __restrict__ W,
    const float* __restrict__ bias, const float* __restrict__ resid,
    float* __restrict__ out, int round_out) {
  extern __shared__ float smg[];
  const uint32_t base = smem_u32(smg);
  // buffer layout (bytes): As[buf] at buf*20480, Bs[buf] at buf*20480+10240
  const int tid = threadIdx.x;
  const int lane = tid & 31, wid = tid >> 5;
  const int g = lane >> 2, tig = lane & 3;
  const int wm = wid & 3, wn = wid >> 2;
  const int mbase = blockIdx.y << 7;
  const int nbase = blockIdx.x << 7;

  const int rowA = (lane & 7) + ((lane >> 3) & 1) * 8;
  const uint32_t offA = (uint32_t)((rowA * 20 + ((lane >> 4) << 2)) << 2);
  const int rowB = (lane & 7) + ((lane >> 4) << 3);
  const uint32_t offB = (uint32_t)((rowB * 20 + (((lane >> 3) & 1) << 2)) << 2);

  uint32_t aOff[2], bOff[4];
#pragma unroll
  for (int mt = 0; mt < 2; mt++)
    aOff[mt] = offA + (uint32_t)(((wm << 5) + (mt << 4)) * 80);
#pragma unroll
  for (int p = 0; p < 4; p++)
    bOff[p] = 10240u + offB + (uint32_t)(((wn << 6) + (p << 4)) * 80);

  // Stage one 128x16 X tile + 128x16 W tile into buffer `buf` (coalesced).
  auto stage = [&](int buf, int kb) {
    uint32_t as = base + (uint32_t)buf * 20480u;
    uint32_t bs = as + 10240u;
#pragma unroll
    for (int j = 0; j < 2; j++) {
      int idx = tid + (j << 8);
      int row = idx >> 2, c4 = (idx & 3) << 2;
      cpa16(as + (uint32_t)((row * 20 + c4) << 2), &X[(size_t)(mbase + row) * DM + kb + c4]);
      cpa16(bs + (uint32_t)((row * 20 + c4) << 2), &W[(size_t)(nbase + row) * DM + kb + c4]);
    }
  };

  float c[2][8][4] = {};

  stage(0, 0);
  cpa_commit();

  for (int kt = 0; kt < 32; kt++) {
    const uint32_t cur = base + (uint32_t)(kt & 1) * 20480u;
    cpa_wait0();
    __syncthreads();
    if (kt + 1 < 32) { stage((kt + 1) & 1, (kt + 1) << 4); cpa_commit(); }

#pragma unroll
    for (int kk = 0; kk < 16; kk += 8) {
      uint32_t af[2][4], bf[4][4];
#pragma unroll
      for (int mt = 0; mt < 2; mt++) ldsm4(af[mt], cur + aOff[mt] + (kk << 2));
#pragma unroll
      for (int p = 0; p < 4; p++) ldsm4(bf[p], cur + bOff[p] + (kk << 2));
#pragma unroll
      for (int mt = 0; mt < 2; mt++)
#pragma unroll
        for (int p = 0; p < 4; p++) {
          mma8(c[mt][2 * p],     af[mt], &bf[p][0]);
          mma8(c[mt][2 * p + 1], af[mt], &bf[p][2]);
        }
    }
  }

#pragma unroll
  for (int mt = 0; mt < 2; mt++) {
    int r = mbase + (wm << 5) + (mt << 4) + g;
#pragma unroll
    for (int nt = 0; nt < 8; nt++) {
      int cc = nbase + (wn << 6) + (nt << 3) + (tig << 1);
      float2 bv = *reinterpret_cast<const float2*>(&bias[cc]);
      float o0 = c[mt][nt][0] + bv.x, o1 = c[mt][nt][1] + bv.y;
      float o2 = c[mt][nt][2] + bv.x, o3 = c[mt][nt][3] + bv.y;
      if (resid != nullptr) {
        float2 r0 = *reinterpret_cast<const float2*>(&resid[(size_t)r * DM + cc]);
        float2 r1 = *reinterpret_cast<const float2*>(&resid[(size_t)(r + 8) * DM + cc]);
        o0 += r0.x; o1 += r0.y; o2 += r1.x; o3 += r1.y;
      }
      if (round_out) {
        o0 = tf32r(o0); o1 = tf32r(o1); o2 = tf32r(o2); o3 = tf32r(o3);
      }
      float2 w0 = {o0, o1}, w1 = {o2, o3};
      *reinterpret_cast<float2*>(&out[(size_t)r * DM + cc]) = w0;
      *reinterpret_cast<float2*>(&out[(size_t)(r + 8) * DM + cc]) = w1;
    }
  }
}

// ---------------------------------------------------------------------------
// V transpose: g_V[b*SEQ+s][h*64+dv] -> g_Vt[(h*2+b)*64+dv][s].
// ---------------------------------------------------------------------------
__global__ __launch_bounds__(256) void vtrans() {
  __shared__ float t[32][33];
  const int s0  = blockIdx.x << 5;
  const int dvt = blockIdx.y;               // over DM/32 = 16
  const int b   = blockIdx.z;
  const int h   = dvt >> 1;
  const int dv0 = (dvt & 1) << 5;
  const int tx = threadIdx.x, ty = threadIdx.y;
#pragma unroll
  for (int k = 0; k < 32; k += 8)
    t[ty + k][tx] = g_V[(size_t)(b * SEQ + s0 + ty + k) * DM + (dvt << 5) + tx];
  __syncthreads();
  const int bh = h * 2 + b;
#pragma unroll
  for (int k = 0; k < 32; k += 8)
    g_Vt[((size_t)bh * DKH + dv0 + ty + k) * SEQ + s0 + tx] = t[tx][ty + k];
}

// ---------------------------------------------------------------------------
// Two-sweep fused attention, TF32 mma + ldmatrix + fully-async staging.
// smem (105984B): Qs[128][68] Ks[64][68] Vt[64][68] Es[128][68] red sinv
// ---------------------------------------------------------------------------
__global__ __launch_bounds__(256, 2) void attn_mma(float* __restrict__ attn_out) {
  extern __shared__ float sm[];
  float (*Qs)[68] = reinterpret_cast<float(*)[68]>(sm);
  float (*Ks)[68] = reinterpret_cast<float(*)[68]>(sm + 8704);
  float (*Vt)[68] = reinterpret_cast<float(*)[68]>(sm + 13056);
  float (*Es)[68] = reinterpret_cast<float(*)[68]>(sm + 17408);
  float (*red)[2] = reinterpret_cast<float(*)[2]>(sm + 26112);
  float* sinv = sm + 26368;

  const int tid = threadIdx.x;
  const int lane = tid & 31, wid = tid >> 5;
  const int g = lane >> 2, tig = lane & 3;
  const int wq = wid >> 1, wn = wid & 1;       // 4q x 2n warps
  const int bh = blockIdx.y;                   // h*2 + b
  const int h = bh >> 1, b = bh & 1;
  const int qbase = blockIdx.x << 7;

  const float* Qg  = g_Q + (size_t)(b * SEQ + qbase) * DM + h * DKH;
  const float* Kg  = g_K + (size_t)(b * SEQ) * DM + h * DKH;
  const float* VTg = g_Vt + (size_t)bh * DKH * SEQ;   // [64][2048]

  const int rowA = (lane & 7) + ((lane >> 3) & 1) * 8;
  const uint32_t offA = (uint32_t)((rowA * 68 + ((lane >> 4) << 2)) << 2);
  const int rowB = (lane & 7) + ((lane >> 4) << 3);
  const uint32_t offB = (uint32_t)((rowB * 68 + (((lane >> 3) & 1) << 2)) << 2);

  const uint32_t ksBase = smem_u32(&Ks[0][0]);
  const uint32_t vtBase = smem_u32(&Vt[0][0]);
  const uint32_t esBase = smem_u32(&Es[0][0]);

  uint32_t qAddr[2], eAddr[2], vAddr[2], kOff[2];
#pragma unroll
  for (int mt = 0; mt < 2; mt++) {
    uint32_t moff = (uint32_t)(((wq << 5) + (mt << 4)) * 272);
    qAddr[mt] = smem_u32(&Qs[0][0]) + offA + moff;
    eAddr[mt] = esBase + offA + moff;
  }
#pragma unroll
  for (int p = 0; p < 2; p++) {
    uint32_t noff = (uint32_t)(((wn << 5) + (p << 4)) * 272);
    kOff[p]  = offB + noff;
    vAddr[p] = vtBase + offB + noff;
  }

  // Stage Q via cp.async (values already tf32)
#pragma unroll
  for (int j = 0; j < 8; j++) {
    int idx = tid + (j << 8);
    int row = idx >> 4, c4 = (idx & 15) << 2;
    cpa16(smem_u32(&Qs[row][c4]), &Qg[(size_t)row * DM + c4]);
  }
  cpa_commit();

  auto stageK = [&](uint32_t dstBase, int kb) {
#pragma unroll
    for (int j = 0; j < 4; j++) {
      int idx = tid + (j << 8);
      int row = idx >> 4, c4 = (idx & 15) << 2;
      cpa16(dstBase + (uint32_t)((row * 68 + c4) << 2), &Kg[(size_t)(kb + row) * DM + c4]);
    }
  };
  auto stageV = [&](int kb) {
#pragma unroll
    for (int j = 0; j < 4; j++) {
      int idx = tid + (j << 8);
      int dv = idx >> 4, c4 = (idx & 15) << 2;
      cpa16(vtBase + (uint32_t)((dv * 68 + c4) << 2), &VTg[(size_t)dv * SEQ + kb + c4]);
    }
  };

  // ---------------- sweep 1: rowsums (K double-buffered: Ks, Es) ----------
  stageK(ksBase, 0);
  cpa_commit();

  float rs[2][2] = {};
  for (int kt = 0; kt < 32; kt++) {
    const uint32_t curBase = (kt & 1) ? esBase : ksBase;
    const uint32_t nxtBase = (kt & 1) ? ksBase : esBase;
    cpa_wait0();
    __syncthreads();
    if (kt + 1 < 32) { stageK(nxtBase, (kt + 1) << 6); cpa_commit(); }

    float s[2][4][4] = {};
#pragma unroll
    for (int d8 = 0; d8 < 64; d8 += 8) {
      uint32_t af[2][4], bf[2][4];
#pragma unroll
      for (int mt = 0; mt < 2; mt++) ldsm4(af[mt], qAddr[mt] + (d8 << 2));
#pragma unroll
      for (int p = 0; p < 2; p++) ldsm4(bf[p], curBase + kOff[p] + (d8 << 2));
#pragma unroll
      for (int mt = 0; mt < 2; mt++)
#pragma unroll
        for (int p = 0; p < 2; p++) {
          mma8(s[mt][2 * p],     af[mt], &bf[p][0]);
          mma8(s[mt][2 * p + 1], af[mt], &bf[p][2]);
        }
    }
#pragma unroll
    for (int mt = 0; mt < 2; mt++)
#pragma unroll
      for (int nt = 0; nt < 4; nt++) {
        rs[mt][0] += __expf(s[mt][nt][0] * INV_TEMP) + __expf(s[mt][nt][1] * INV_TEMP);
        rs[mt][1] += __expf(s[mt][nt][2] * INV_TEMP) + __expf(s[mt][nt][3] * INV_TEMP);
      }
  }
  __syncthreads();

#pragma unroll
  for (int mt = 0; mt < 2; mt++)
#pragma unroll
    for (int u = 0; u < 2; u++) {
      rs[mt][u] += __shfl_xor_sync(0xffffffffu, rs[mt][u], 1);
      rs[mt][u] += __shfl_xor_sync(0xffffffffu, rs[mt][u], 2);
    }
  if (tig == 0) {
#pragma unroll
    for (int mt = 0; mt < 2; mt++)
#pragma unroll
      for (int u = 0; u < 2; u++)
        red[(wq << 5) + (mt << 4) + (u << 3) + g][wn] = rs[mt][u];
  }
  __syncthreads();
  if (tid < 128) sinv[tid] = 1.0f / (red[tid][0] + red[tid][1]);
  __syncthreads();

  float inv[2][2];
#pragma unroll
  for (int mt = 0; mt < 2; mt++) {
    inv[mt][0] = sinv[(wq << 5) + (mt << 4) + g];
    inv[mt][1] = sinv[(wq << 5) + (mt << 4) + 8 + g];
  }
  __syncthreads();

  // ---------------- sweep 2: pipelined normalized attn + context ----------
  stageK(ksBase, 0); cpa_commit();
  stageV(0);         cpa_commit();

  float cx[2][4][4] = {};
  for (int kt = 0; kt < 32; kt++) {
    const int kb = kt << 6;
    cpa_wait1();                 // K(kt) complete (V(kt) may still fly)
    __syncthreads();

    // Scores
    float s[2][4][4] = {};
#pragma unroll
    for (int d8 = 0; d8 < 64; d8 += 8) {
      uint32_t af[2][4], bf[2][4];
#pragma unroll
      for (int mt = 0; mt < 2; mt++) ldsm4(af[mt], qAddr[mt] + (d8 << 2));
#pragma unroll
      for (int p = 0; p < 2; p++) ldsm4(bf[p], ksBase + kOff[p] + (d8 << 2));
#pragma unroll
      for (int mt = 0; mt < 2; mt++)
#pragma unroll
        for (int p = 0; p < 2; p++) {
          mma8(s[mt][2 * p],     af[mt], &bf[p][0]);
          mma8(s[mt][2 * p + 1], af[mt], &bf[p][2]);
        }
    }

    // exp, normalize, tf32-round -> Es
#pragma unroll
    for (int mt = 0; mt < 2; mt++) {
      int r0 = (wq << 5) + (mt << 4) + g;
#pragma unroll
      for (int nt = 0; nt < 4; nt++) {
        int c0 = (wn << 5) + (nt << 3) + (tig << 1);
        float e0 = __expf(s[mt][nt][0] * INV_TEMP) * inv[mt][0];
        float e1 = __expf(s[mt][nt][1] * INV_TEMP) * inv[mt][0];
        float e2 = __expf(s[mt][nt][2] * INV_TEMP) * inv[mt][1];
        float e3 = __expf(s[mt][nt][3] * INV_TEMP) * inv[mt][1];
        float2 t0 = {tf32r(e0), tf32r(e1)}, t1 = {tf32r(e2), tf32r(e3)};
        *reinterpret_cast<float2*>(&Es[r0][c0]) = t0;
        *reinterpret_cast<float2*>(&Es[r0 + 8][c0]) = t1;
      }
    }
    cpa_wait0();                 // V(kt) complete
    __syncthreads();
    if (kt + 1 < 32) { stageK(ksBase, (kt + 1) << 6); cpa_commit(); }  // Ks free

    // ctx += E @ V
#pragma unroll
    for (int k8 = 0; k8 < 64; k8 += 8) {
      uint32_t af[2][4], bf[2][4];
#pragma unroll
      for (int mt = 0; mt < 2; mt++) ldsm4(af[mt], eAddr[mt] + (k8 << 2));
#pragma unroll
      for (int p = 0; p < 2; p++) ldsm4(bf[p], vAddr[p] + (k8 << 2));
#pragma unroll
      for (int mt = 0; mt < 2; mt++)
#pragma unroll
        for (int p = 0; p < 2; p++) {
          mma8(cx[mt][2 * p],     af[mt], &bf[p][0]);
          mma8(cx[mt][2 * p + 1], af[mt], &bf[p][2]);
        }
    }

    // Coalesced attn store from Es
#pragma unroll
    for (int j = 0; j < 8; j++) {
      int idx = tid + (j << 8);
      int row = idx >> 4, c4 = (idx & 15) << 2;
      float4 e = *reinterpret_cast<const float4*>(&Es[row][c4]);
      size_t go = ((size_t)bh * SEQ + qbase + row) * SEQ + kb + c4;
      *reinterpret_cast<float4*>(&attn_out[go]) = e;
    }
    __syncthreads();
    if (kt + 1 < 32) { stageV((kt + 1) << 6); cpa_commit(); }          // Vt free
  }

  // Write context (merged heads), tf32-rounded for the async fc GEMM
#pragma unroll
  for (int mt = 0; mt < 2; mt++) {
    int r = b * SEQ + qbase + (wq << 5) + (mt << 4) + g;
#pragma unroll
    for (int nt = 0; nt < 4; nt++) {
      int cc = h * DKH + (wn << 5) + (nt << 3) + (tig << 1);
      float2 w0 = {tf32r(cx[mt][nt][0]), tf32r(cx[mt][nt][1])};
      float2 w1 = {tf32r(cx[mt][nt][2]), tf32r(cx[mt][nt][3])};
      *reinterpret_cast<float2*>(&g_ctx[(size_t)r * DM + cc]) = w0;
      *reinterpret_cast<float2*>(&g_ctx[(size_t)(r + 8) * DM + cc]) = w1;
    }
  }
}

// ---------------------------------------------------------------------------
// LayerNorm over last dim (512), one block per row.
// ---------------------------------------------------------------------------
__global__ __launch_bounds__(256) void ln_kernel(
    const float* __restrict__ gamma, const float* __restrict__ beta,
    float* __restrict__ y) {
  __shared__ float warp_s[8], warp_q[8];
  __shared__ float s_mu, s_rstd;
  const int row = blockIdx.x;
  const int tid = threadIdx.x;
  const float* x = g_x + (size_t)row * DM;

  float v0 = x[tid], v1 = x[tid + 256];
  float s = v0 + v1;
  float q = v0 * v0 + v1 * v1;
#pragma unroll
  for (int o = 16; o > 0; o >>= 1) {
    s += __shfl_xor_sync(0xffffffffu, s, o);
    q += __shfl_xor_sync(0xffffffffu, q, o);
  }
  if ((tid & 31) == 0) { warp_s[tid >> 5] = s; warp_q[tid >> 5] = q; }
  __syncthreads();
  if (tid == 0) {
    float ss = 0.f, qq = 0.f;
#pragma unroll
    for (int i = 0; i < 8; i++) { ss += warp_s[i]; qq += warp_q[i]; }
    float mu = ss * (1.0f / DM);
    float var = qq * (1.0f / DM) - mu * mu;
    s_mu = mu;
    s_rstd = rsqrtf(var + LN_EPS);
  }
  __syncthreads();
  float mu = s_mu, r = s_rstd;
  y[(size_t)row * DM + tid]       = (v0 - mu) * r * gamma[tid] + beta[tid];
  y[(size_t)row * DM + tid + 256] = (v1 - mu) * r * gamma[tid + 256] + beta[tid + 256];
}

// ---------------------------------------------------------------------------
extern "C" void kernel_launch(void* const* d_in, const int* in_sizes, int n_in,
                              void* d_out, int out_size) {
  const float* q     = (const float*)d_in[0];
  const float* k     = (const float*)d_in[1];
  const float* v     = (const float*)d_in[2];
  const float* Wq    = (const float*)d_in[3];
  const float* bq    = (const float*)d_in[4];
  const float* Wk    = (const float*)d_in[5];
  const float* bk    = (const float*)d_in[6];
  const float* Wv    = (const float*)d_in[7];
  const float* bv    = (const float*)d_in[8];
  const float* Wfc   = (const float*)d_in[9];
  const float* bfc   = (const float*)d_in[10];
  const float* gamma = (const float*)d_in[11];
  const float* beta  = (const float*)d_in[12];

  float* out = (float*)d_out;                       // y: [2,2048,512]
  float* attn_out = out + (size_t)MM * DM;          // attn: [16,2048,2048]

  float *gQ, *gK, *gV, *gctx, *gx;
  float *gqr, *gkr, *gvr, *gwq, *gwk, *gwv, *gwfc;
  cudaGetSymbolAddress((void**)&gQ, g_Q);
  cudaGetSymbolAddress((void**)&gK, g_K);
  cudaGetSymbolAddress((void**)&gV, g_V);
  cudaGetSymbolAddress((void**)&gctx, g_ctx);
  cudaGetSymbolAddress((void**)&gx, g_x);
  cudaGetSymbolAddress((void**)&gqr, g_qr);
  cudaGetSymbolAddress((void**)&gkr, g_kr);
  cudaGetSymbolAddress((void**)&gvr, g_vr);
  cudaGetSymbolAddress((void**)&gwq, g_wq);
  cudaGetSymbolAddress((void**)&gwk, g_wk);
  cudaGetSymbolAddress((void**)&gwv, g_wv);
  cudaGetSymbolAddress((void**)&gwfc, g_wfc);

  cudaFuncSetAttribute(attn_mma, cudaFuncAttributeMaxDynamicSharedMemorySize, 105984);
  cudaFuncSetAttribute(gemm_mma, cudaFuncAttributeMaxDynamicSharedMemorySize, 81920);

  // Pre-round inputs + weights to tf32 (bit-identical to old in-kernel cvt)
  const unsigned nIn4 = (unsigned)(MM * DM / 4 / 256);   // 2048 blocks
  const unsigned nW4  = (unsigned)(DM * DM / 4 / 256);   // 256 blocks
  round_tf32<<<nIn4, 256>>>(q, gqr);
  round_tf32<<<nIn4, 256>>>(k, gkr);
  round_tf32<<<nIn4, 256>>>(v, gvr);
  round_tf32<<<nW4, 256>>>(Wq, gwq);
  round_tf32<<<nW4, 256>>>(Wk, gwk);
  round_tf32<<<nW4, 256>>>(Wv, gwv);
  round_tf32<<<nW4, 256>>>(Wfc, gwfc);

  dim3 gg(DM / 128, MM / 128);     // (4, 32) = 128 CTAs
  gemm_mma<<<gg, 256, 81920>>>(gqr, gwq, bq, nullptr, gQ, 1);
  gemm_mma<<<gg, 256, 81920>>>(gkr, gwk, bk, nullptr, gK, 1);
  gemm_mma<<<gg, 256, 81920>>>(gvr, gwv, bv, nullptr, gV, 1);

  dim3 gt(SEQ / 32, DM / 32, B2);  // (64, 16, 2)
  vtrans<<<gt, dim3(32, 8)>>>();

  dim3 ga(SEQ / 128, NH * B2);     // (16, 16)
  attn_mma<<<ga, 256, 105984>>>(attn_out);

  gemm_mma<<<gg, 256, 81920>>>(gctx, gwfc, bfc, q, gx, 0);
  ln_kernel<<<MM, 256>>>(gamma, beta, out);
}

// round 14
// speedup vs baseline: 1.8743x; 1.0946x over previous
#include <cuda_runtime.h>
#include <cstdint>
#include <cstddef>

namespace {
constexpr int B2  = 2;
constexpr int SEQ = 2048;
constexpr int DM  = 512;
constexpr int NH  = 8;
constexpr int DKH = 64;
constexpr int MM  = B2 * SEQ;              // 4096
constexpr float INV_TEMP = 0.04419417382415922f;  // 1/sqrt(512)
constexpr float LN_EPS = 1e-5f;
}

// Scratch (device globals — allocations are forbidden)
__device__ float g_Q[MM * DM];
__device__ float g_K[MM * DM];
__device__ float g_V[MM * DM];
__device__ float g_Vt[NH * B2 * DKH * SEQ];   // [bh][dv][seq], bh = h*2+b
__device__ float g_ctx[MM * DM];
__device__ float g_x[MM * DM];
__device__ float g_qr[MM * DM];               // tf32-rounded inputs
__device__ float g_kr[MM * DM];
__device__ float g_vr[MM * DM];
__device__ float g_wq[DM * DM];               // tf32-rounded weights
__device__ float g_wk[DM * DM];
__device__ float g_wv[DM * DM];
__device__ float g_wfc[DM * DM];

__device__ __forceinline__ float tf32r(float x) {
  uint32_t o;
  asm("cvt.rna.tf32.f32 %0, %1;" : "=r"(o) : "f"(x));
  return __uint_as_float(o);
}

__device__ __forceinline__ void mma8(float* c, const uint32_t* a, const uint32_t* b) {
  asm volatile(
      "mma.sync.aligned.m16n8k8.row.col.f32.tf32.tf32.f32 "
      "{%0,%1,%2,%3}, {%4,%5,%6,%7}, {%8,%9}, {%0,%1,%2,%3};"
      : "+f"(c[0]), "+f"(c[1]), "+f"(c[2]), "+f"(c[3])
      : "r"(a[0]), "r"(a[1]), "r"(a[2]), "r"(a[3]), "r"(b[0]), "r"(b[1]));
}

__device__ __forceinline__ void ldsm4(uint32_t* r, uint32_t addr) {
  asm volatile("ldmatrix.sync.aligned.m8n8.x4.shared.b16 {%0,%1,%2,%3}, [%4];"
               : "=r"(r[0]), "=r"(r[1]), "=r"(r[2]), "=r"(r[3]) : "r"(addr));
}

__device__ __forceinline__ uint32_t smem_u32(const void* p) {
  return (uint32_t)__cvta_generic_to_shared(p);
}

__device__ __forceinline__ void cpa16(uint32_t dst, const void* src) {
  asm volatile("cp.async.cg.shared.global [%0], [%1], 16;" :: "r"(dst), "l"(src));
}
__device__ __forceinline__ void cpa_commit() {
  asm volatile("cp.async.commit_group;");
}
__device__ __forceinline__ void cpa_wait0() {
  asm volatile("cp.async.wait_group 0;");
}
__device__ __forceinline__ void cpa_wait1() {
  asm volatile("cp.async.wait_group 1;");
}

// ---------------------------------------------------------------------------
// Fused tf32 rounding of all 7 tensors in one launch.
// Segments (in float4 blocks of 256): q,k,v = 2048 blocks each; 4 weights =
// 256 blocks each. Total 7168 blocks.
// ---------------------------------------------------------------------------
__global__ __launch_bounds__(256) void round_all(
    const float* __restrict__ q, const float* __restrict__ k,
    const float* __restrict__ v, const float* __restrict__ wq,
    const float* __restrict__ wk, const float* __restrict__ wv,
    const float* __restrict__ wfc) {
  int blk = blockIdx.x;
  const float* src;
  float* dst;
  if (blk < 6144) {
    int seg = blk >> 11;            // 0..2
    src = seg == 0 ? q : (seg == 1 ? k : v);
    dst = seg == 0 ? g_qr : (seg == 1 ? g_kr : g_vr);
    blk &= 2047;
  } else {
    int seg = (blk - 6144) >> 8;    // 0..3
    src = seg == 0 ? wq : (seg == 1 ? wk : (seg == 2 ? wv : wfc));
    dst = seg == 0 ? g_wq : (seg == 1 ? g_wk : (seg == 2 ? g_wv : g_wfc));
    blk = (blk - 6144) & 255;
  }
  size_t i = (size_t)blk * 256 + threadIdx.x;
  float4 x = reinterpret_cast<const float4*>(src)[i];
  x.x = tf32r(x.x); x.y = tf32r(x.y); x.z = tf32r(x.z); x.w = tf32r(x.w);
  reinterpret_cast<float4*>(dst)[i] = x;
}

// ---------------------------------------------------------------------------
// Dense GEMM core (device function), 1xTF32, cp.async double-buffered.
// CTA 128x128, 8 warps (4m x 2n), warp 32x64, K-step 16, 1 barrier/iter.
// Dynamic smem 81920B: 2 x (As+Bs), stride 20.
// ---------------------------------------------------------------------------
__device__ __forceinline__ void gemm_body(
    const float* __restrict__ X, const float* __restrict__ W,
    const float* __restrict__ bias, const float* __restrict__ resid,
    float* __restrict__ out, int round_out, int mbase, int nbase) {
  extern __shared__ float smg[];
  const uint32_t base = smem_u32(smg);
  const int tid = threadIdx.x;
  const int lane = tid & 31, wid = tid >> 5;
  const int g = lane >> 2, tig = lane & 3;
  const int wm = wid & 3, wn = wid >> 2;

  const int rowA = (lane & 7) + ((lane >> 3) & 1) * 8;
  const uint32_t offA = (uint32_t)((rowA * 20 + ((lane >> 4) << 2)) << 2);
  const int rowB = (lane & 7) + ((lane >> 4) << 3);
  const uint32_t offB = (uint32_t)((rowB * 20 + (((lane >> 3) & 1) << 2)) << 2);

  uint32_t aOff[2], bOff[4];
#pragma unroll
  for (int mt = 0; mt < 2; mt++)
    aOff[mt] = offA + (uint32_t)(((wm << 5) + (mt << 4)) * 80);
#pragma unroll
  for (int p = 0; p < 4; p++)
    bOff[p] = 10240u + offB + (uint32_t)(((wn << 6) + (p << 4)) * 80);

  auto stage = [&](int buf, int kb) {
    uint32_t as = base + (uint32_t)buf * 20480u;
    uint32_t bs = as + 10240u;
#pragma unroll
    for (int j = 0; j < 2; j++) {
      int idx = tid + (j << 8);
      int row = idx >> 2, c4 = (idx & 3) << 2;
      cpa16(as + (uint32_t)((row * 20 + c4) << 2), &X[(size_t)(mbase + row) * DM + kb + c4]);
      cpa16(bs + (uint32_t)((row * 20 + c4) << 2), &W[(size_t)(nbase + row) * DM + kb + c4]);
    }
  };

  float c[2][8][4] = {};

  stage(0, 0);
  cpa_commit();

  for (int kt = 0; kt < 32; kt++) {
    const uint32_t cur = base + (uint32_t)(kt & 1) * 20480u;
    cpa_wait0();
    __syncthreads();
    if (kt + 1 < 32) { stage((kt + 1) & 1, (kt + 1) << 4); cpa_commit(); }

#pragma unroll
    for (int kk = 0; kk < 16; kk += 8) {
      uint32_t af[2][4], bf[4][4];
#pragma unroll
      for (int mt = 0; mt < 2; mt++) ldsm4(af[mt], cur + aOff[mt] + (kk << 2));
#pragma unroll
      for (int p = 0; p < 4; p++) ldsm4(bf[p], cur + bOff[p] + (kk << 2));
#pragma unroll
      for (int mt = 0; mt < 2; mt++)
#pragma unroll
        for (int p = 0; p < 4; p++) {
          mma8(c[mt][2 * p],     af[mt], &bf[p][0]);
          mma8(c[mt][2 * p + 1], af[mt], &bf[p][2]);
        }
    }
  }

#pragma unroll
  for (int mt = 0; mt < 2; mt++) {
    int r = mbase + (wm << 5) + (mt << 4) + g;
#pragma unroll
    for (int nt = 0; nt < 8; nt++) {
      int cc = nbase + (wn << 6) + (nt << 3) + (tig << 1);
      float2 bv = *reinterpret_cast<const float2*>(&bias[cc]);
      float o0 = c[mt][nt][0] + bv.x, o1 = c[mt][nt][1] + bv.y;
      float o2 = c[mt][nt][2] + bv.x, o3 = c[mt][nt][3] + bv.y;
      if (resid != nullptr) {
        float2 r0 = *reinterpret_cast<const float2*>(&resid[(size_t)r * DM + cc]);
        float2 r1 = *reinterpret_cast<const float2*>(&resid[(size_t)(r + 8) * DM + cc]);
        o0 += r0.x; o1 += r0.y; o2 += r1.x; o3 += r1.y;
      }
      if (round_out) {
        o0 = tf32r(o0); o1 = tf32r(o1); o2 = tf32r(o2); o3 = tf32r(o3);
      }
      float2 w0 = {o0, o1}, w1 = {o2, o3};
      *reinterpret_cast<float2*>(&out[(size_t)r * DM + cc]) = w0;
      *reinterpret_cast<float2*>(&out[(size_t)(r + 8) * DM + cc]) = w1;
    }
  }
}

// Batched Q/K/V projections in ONE launch: grid.z selects the problem.
__global__ __launch_bounds__(256) void gemm_qkv(
    const float* __restrict__ b0, const float* __restrict__ b1,
    const float* __restrict__ b2) {
  const int z = blockIdx.z;
  const float* X = z == 0 ? g_qr : (z == 1 ? g_kr : g_vr);
  const float* W = z == 0 ? g_wq : (z == 1 ? g_wk : g_wv);
  const float* bias = z == 0 ? b0 : (z == 1 ? b1 : b2);
  float* out = z == 0 ? g_Q : (z == 1 ? g_K : g_V);
  gemm_body(X, W, bias, nullptr, out, 1, blockIdx.y << 7, blockIdx.x << 7);
}

// Single fc GEMM (+residual) launch.
__global__ __launch_bounds__(256) void gemm_fc(
    const float* __restrict__ bias, const float* __restrict__ resid) {
  gemm_body(g_ctx, g_wfc, bias, resid, g_x, 0, blockIdx.y << 7, blockIdx.x << 7);
}

// ---------------------------------------------------------------------------
// V transpose: g_V[b*SEQ+s][h*64+dv] -> g_Vt[(h*2+b)*64+dv][s].
// ---------------------------------------------------------------------------
__global__ __launch_bounds__(256) void vtrans() {
  __shared__ float t[32][33];
  const int s0  = blockIdx.x << 5;
  const int dvt = blockIdx.y;               // over DM/32 = 16
  const int b   = blockIdx.z;
  const int h   = dvt >> 1;
  const int dv0 = (dvt & 1) << 5;
  const int tx = threadIdx.x, ty = threadIdx.y;
#pragma unroll
  for (int k = 0; k < 32; k += 8)
    t[ty + k][tx] = g_V[(size_t)(b * SEQ + s0 + ty + k) * DM + (dvt << 5) + tx];
  __syncthreads();
  const int bh = h * 2 + b;
#pragma unroll
  for (int k = 0; k < 32; k += 8)
    g_Vt[((size_t)bh * DKH + dv0 + ty + k) * SEQ + s0 + tx] = t[tx][ty + k];
}

// ---------------------------------------------------------------------------
// Two-sweep fused attention, TF32 mma + ldmatrix + fully-async staging.
// smem (105984B): Qs[128][68] Ks[64][68] Vt[64][68] Es[128][68] red sinv
// ---------------------------------------------------------------------------
__global__ __launch_bounds__(256, 2) void attn_mma(float* __restrict__ attn_out) {
  extern __shared__ float sm[];
  float (*Qs)[68] = reinterpret_cast<float(*)[68]>(sm);
  float (*Ks)[68] = reinterpret_cast<float(*)[68]>(sm + 8704);
  float (*Vt)[68] = reinterpret_cast<float(*)[68]>(sm + 13056);
  float (*Es)[68] = reinterpret_cast<float(*)[68]>(sm + 17408);
  float (*red)[2] = reinterpret_cast<float(*)[2]>(sm + 26112);
  float* sinv = sm + 26368;

  const int tid = threadIdx.x;
  const int lane = tid & 31, wid = tid >> 5;
  const int g = lane >> 2, tig = lane & 3;
  const int wq = wid >> 1, wn = wid & 1;       // 4q x 2n warps
  const int bh = blockIdx.y;                   // h*2 + b
  const int h = bh >> 1, b = bh & 1;
  const int qbase = blockIdx.x << 7;

  const float* Qg  = g_Q + (size_t)(b * SEQ + qbase) * DM + h * DKH;
  const float* Kg  = g_K + (size_t)(b * SEQ) * DM + h * DKH;
  const float* VTg = g_Vt + (size_t)bh * DKH * SEQ;   // [64][2048]

  const int rowA = (lane & 7) + ((lane >> 3) & 1) * 8;
  const uint32_t offA = (uint32_t)((rowA * 68 + ((lane >> 4) << 2)) << 2);
  const int rowB = (lane & 7) + ((lane >> 4) << 3);
  const uint32_t offB = (uint32_t)((rowB * 68 + (((lane >> 3) & 1) << 2)) << 2);

  const uint32_t ksBase = smem_u32(&Ks[0][0]);
  const uint32_t vtBase = smem_u32(&Vt[0][0]);
  const uint32_t esBase = smem_u32(&Es[0][0]);

  uint32_t qAddr[2], eAddr[2], vAddr[2], kOff[2];
#pragma unroll
  for (int mt = 0; mt < 2; mt++) {
    uint32_t moff = (uint32_t)(((wq << 5) + (mt << 4)) * 272);
    qAddr[mt] = smem_u32(&Qs[0][0]) + offA + moff;
    eAddr[mt] = esBase + offA + moff;
  }
#pragma unroll
  for (int p = 0; p < 2; p++) {
    uint32_t noff = (uint32_t)(((wn << 5) + (p << 4)) * 272);
    kOff[p]  = offB + noff;
    vAddr[p] = vtBase + offB + noff;
  }

  // Stage Q via cp.async (values already tf32)
#pragma unroll
  for (int j = 0; j < 8; j++) {
    int idx = tid + (j << 8);
    int row = idx >> 4, c4 = (idx & 15) << 2;
    cpa16(smem_u32(&Qs[row][c4]), &Qg[(size_t)row * DM + c4]);
  }
  cpa_commit();

  auto stageK = [&](uint32_t dstBase, int kb) {
#pragma unroll
    for (int j = 0; j < 4; j++) {
      int idx = tid + (j << 8);
      int row = idx >> 4, c4 = (idx & 15) << 2;
      cpa16(dstBase + (uint32_t)((row * 68 + c4) << 2), &Kg[(size_t)(kb + row) * DM + c4]);
    }
  };
  auto stageV = [&](int kb) {
#pragma unroll
    for (int j = 0; j < 4; j++) {
      int idx = tid + (j << 8);
      int dv = idx >> 4, c4 = (idx & 15) << 2;
      cpa16(vtBase + (uint32_t)((dv * 68 + c4) << 2), &VTg[(size_t)dv * SEQ + kb + c4]);
    }
  };

  // ---------------- sweep 1: rowsums (K double-buffered: Ks, Es) ----------
  stageK(ksBase, 0);
  cpa_commit();

  float rs[2][2] = {};
  for (int kt = 0; kt < 32; kt++) {
    const uint32_t curBase = (kt & 1) ? esBase : ksBase;
    const uint32_t nxtBase = (kt & 1) ? ksBase : esBase;
    cpa_wait0();
    __syncthreads();
    if (kt + 1 < 32) { stageK(nxtBase, (kt + 1) << 6); cpa_commit(); }

    float s[2][4][4] = {};
#pragma unroll
    for (int d8 = 0; d8 < 64; d8 += 8) {
      uint32_t af[2][4], bf[2][4];
#pragma unroll
      for (int mt = 0; mt < 2; mt++) ldsm4(af[mt], qAddr[mt] + (d8 << 2));
#pragma unroll
      for (int p = 0; p < 2; p++) ldsm4(bf[p], curBase + kOff[p] + (d8 << 2));
#pragma unroll
      for (int mt = 0; mt < 2; mt++)
#pragma unroll
        for (int p = 0; p < 2; p++) {
          mma8(s[mt][2 * p],     af[mt], &bf[p][0]);
          mma8(s[mt][2 * p + 1], af[mt], &bf[p][2]);
        }
    }
#pragma unroll
    for (int mt = 0; mt < 2; mt++)
#pragma unroll
      for (int nt = 0; nt < 4; nt++) {
        rs[mt][0] += __expf(s[mt][nt][0] * INV_TEMP) + __expf(s[mt][nt][1] * INV_TEMP);
        rs[mt][1] += __expf(s[mt][nt][2] * INV_TEMP) + __expf(s[mt][nt][3] * INV_TEMP);
      }
  }
  __syncthreads();

#pragma unroll
  for (int mt = 0; mt < 2; mt++)
#pragma unroll
    for (int u = 0; u < 2; u++) {
      rs[mt][u] += __shfl_xor_sync(0xffffffffu, rs[mt][u], 1);
      rs[mt][u] += __shfl_xor_sync(0xffffffffu, rs[mt][u], 2);
    }
  if (tig == 0) {
#pragma unroll
    for (int mt = 0; mt < 2; mt++)
#pragma unroll
      for (int u = 0; u < 2; u++)
        red[(wq << 5) + (mt << 4) + (u << 3) + g][wn] = rs[mt][u];
  }
  __syncthreads();
  if (tid < 128) sinv[tid] = 1.0f / (red[tid][0] + red[tid][1]);
  __syncthreads();

  float inv[2][2];
#pragma unroll
  for (int mt = 0; mt < 2; mt++) {
    inv[mt][0] = sinv[(wq << 5) + (mt << 4) + g];
    inv[mt][1] = sinv[(wq << 5) + (mt << 4) + 8 + g];
  }
  __syncthreads();

  // ---------------- sweep 2: pipelined normalized attn + context ----------
  stageK(ksBase, 0); cpa_commit();
  stageV(0);         cpa_commit();

  float cx[2][4][4] = {};
  for (int kt = 0; kt < 32; kt++) {
    const int kb = kt << 6;
    cpa_wait1();                 // K(kt) complete (V(kt) may still fly)
    __syncthreads();

    // Scores
    float s[2][4][4] = {};
#pragma unroll
    for (int d8 = 0; d8 < 64; d8 += 8) {
      uint32_t af[2][4], bf[2][4];
#pragma unroll
      for (int mt = 0; mt < 2; mt++) ldsm4(af[mt], qAddr[mt] + (d8 << 2));
#pragma unroll
      for (int p = 0; p < 2; p++) ldsm4(bf[p], ksBase + kOff[p] + (d8 << 2));
#pragma unroll
      for (int mt = 0; mt < 2; mt++)
#pragma unroll
        for (int p = 0; p < 2; p++) {
          mma8(s[mt][2 * p],     af[mt], &bf[p][0]);
          mma8(s[mt][2 * p + 1], af[mt], &bf[p][2]);
        }
    }

    // exp, normalize, tf32-round -> Es
#pragma unroll
    for (int mt = 0; mt < 2; mt++) {
      int r0 = (wq << 5) + (mt << 4) + g;
#pragma unroll
      for (int nt = 0; nt < 4; nt++) {
        int c0 = (wn << 5) + (nt << 3) + (tig << 1);
        float e0 = __expf(s[mt][nt][0] * INV_TEMP) * inv[mt][0];
        float e1 = __expf(s[mt][nt][1] * INV_TEMP) * inv[mt][0];
        float e2 = __expf(s[mt][nt][2] * INV_TEMP) * inv[mt][1];
        float e3 = __expf(s[mt][nt][3] * INV_TEMP) * inv[mt][1];
        float2 t0 = {tf32r(e0), tf32r(e1)}, t1 = {tf32r(e2), tf32r(e3)};
        *reinterpret_cast<float2*>(&Es[r0][c0]) = t0;
        *reinterpret_cast<float2*>(&Es[r0 + 8][c0]) = t1;
      }
    }
    cpa_wait0();                 // V(kt) complete
    __syncthreads();
    if (kt + 1 < 32) { stageK(ksBase, (kt + 1) << 6); cpa_commit(); }  // Ks free

    // ctx += E @ V
#pragma unroll
    for (int k8 = 0; k8 < 64; k8 += 8) {
      uint32_t af[2][4], bf[2][4];
#pragma unroll
      for (int mt = 0; mt < 2; mt++) ldsm4(af[mt], eAddr[mt] + (k8 << 2));
#pragma unroll
      for (int p = 0; p < 2; p++) ldsm4(bf[p], vAddr[p] + (k8 << 2));
#pragma unroll
      for (int mt = 0; mt < 2; mt++)
#pragma unroll
        for (int p = 0; p < 2; p++) {
          mma8(cx[mt][2 * p],     af[mt], &bf[p][0]);
          mma8(cx[mt][2 * p + 1], af[mt], &bf[p][2]);
        }
    }

    // Coalesced attn store from Es
#pragma unroll
    for (int j = 0; j < 8; j++) {
      int idx = tid + (j << 8);
      int row = idx >> 4, c4 = (idx & 15) << 2;
      float4 e = *reinterpret_cast<const float4*>(&Es[row][c4]);
      size_t go = ((size_t)bh * SEQ + qbase + row) * SEQ + kb + c4;
      *reinterpret_cast<float4*>(&attn_out[go]) = e;
    }
    __syncthreads();
    if (kt + 1 < 32) { stageV((kt + 1) << 6); cpa_commit(); }          // Vt free
  }

  // Write context (merged heads), tf32-rounded for the async fc GEMM
#pragma unroll
  for (int mt = 0; mt < 2; mt++) {
    int r = b * SEQ + qbase + (wq << 5) + (mt << 4) + g;
#pragma unroll
    for (int nt = 0; nt < 4; nt++) {
      int cc = h * DKH + (wn << 5) + (nt << 3) + (tig << 1);
      float2 w0 = {tf32r(cx[mt][nt][0]), tf32r(cx[mt][nt][1])};
      float2 w1 = {tf32r(cx[mt][nt][2]), tf32r(cx[mt][nt][3])};
      *reinterpret_cast<float2*>(&g_ctx[(size_t)r * DM + cc]) = w0;
      *reinterpret_cast<float2*>(&g_ctx[(size_t)(r + 8) * DM + cc]) = w1;
    }
  }
}

// ---------------------------------------------------------------------------
// LayerNorm over last dim (512), one block per row.
// ---------------------------------------------------------------------------
__global__ __launch_bounds__(256) void ln_kernel(
    const float* __restrict__ gamma, const float* __restrict__ beta,
    float* __restrict__ y) {
  __shared__ float warp_s[8], warp_q[8];
  __shared__ float s_mu, s_rstd;
  const int row = blockIdx.x;
  const int tid = threadIdx.x;
  const float* x = g_x + (size_t)row * DM;

  float v0 = x[tid], v1 = x[tid + 256];
  float s = v0 + v1;
  float q = v0 * v0 + v1 * v1;
#pragma unroll
  for (int o = 16; o > 0; o >>= 1) {
    s += __shfl_xor_sync(0xffffffffu, s, o);
    q += __shfl_xor_sync(0xffffffffu, q, o);
  }
  if ((tid & 31) == 0) { warp_s[tid >> 5] = s; warp_q[tid >> 5] = q; }
  __syncthreads();
  if (tid == 0) {
    float ss = 0.f, qq = 0.f;
#pragma unroll
    for (int i = 0; i < 8; i++) { ss += warp_s[i]; qq += warp_q[i]; }
    float mu = ss * (1.0f / DM);
    float var = qq * (1.0f / DM) - mu * mu;
    s_mu = mu;
    s_rstd = rsqrtf(var + LN_EPS);
  }
  __syncthreads();
  float mu = s_mu, r = s_rstd;
  y[(size_t)row * DM + tid]       = (v0 - mu) * r * gamma[tid] + beta[tid];
  y[(size_t)row * DM + tid + 256] = (v1 - mu) * r * gamma[tid + 256] + beta[tid + 256];
}

// ---------------------------------------------------------------------------
extern "C" void kernel_launch(void* const* d_in, const int* in_sizes, int n_in,
                              void* d_out, int out_size) {
  const float* q     = (const float*)d_in[0];
  const float* k     = (const float*)d_in[1];
  const float* v     = (const float*)d_in[2];
  const float* Wq    = (const float*)d_in[3];
  const float* bq    = (const float*)d_in[4];
  const float* Wk    = (const float*)d_in[5];
  const float* bk    = (const float*)d_in[6];
  const float* Wv    = (const float*)d_in[7];
  const float* bv    = (const float*)d_in[8];
  const float* Wfc   = (const float*)d_in[9];
  const float* bfc   = (const float*)d_in[10];
  const float* gamma = (const float*)d_in[11];
  const float* beta  = (const float*)d_in[12];

  float* out = (float*)d_out;                       // y: [2,2048,512]
  float* attn_out = out + (size_t)MM * DM;          // attn: [16,2048,2048]

  cudaFuncSetAttribute(attn_mma, cudaFuncAttributeMaxDynamicSharedMemorySize, 105984);
  cudaFuncSetAttribute(gemm_qkv, cudaFuncAttributeMaxDynamicSharedMemorySize, 81920);
  cudaFuncSetAttribute(gemm_fc,  cudaFuncAttributeMaxDynamicSharedMemorySize, 81920);

  // One fused rounding pass for all inputs + weights (7168 blocks)
  round_all<<<7168, 256>>>(q, k, v, Wq, Wk, Wv, Wfc);

  // Batched Q/K/V projections: grid (4, 32, 3) = 384 CTAs in one launch
  dim3 gq(DM / 128, MM / 128, 3);
  gemm_qkv<<<gq, 256, 81920>>>(bq, bk, bv);

  dim3 gt(SEQ / 32, DM / 32, B2);  // (64, 16, 2)
  vtrans<<<gt, dim3(32, 8)>>>();

  dim3 ga(SEQ / 128, NH * B2);     // (16, 16)
  attn_mma<<<ga, 256, 105984>>>(attn_out);

  dim3 gg(DM / 128, MM / 128);     // (4, 32)
  gemm_fc<<<gg, 256, 81920>>>(bfc, q);
  ln_kernel<<<MM, 256>>>(gamma, beta, out);
}